// round 11
// baseline (speedup 1.0000x reference)
#include <cuda_runtime.h>
#include <cuda_bf16.h>
#include <math.h>
#include <cstdint>

// Problem constants
#define B_    2
#define N_    4096
#define C_    256
#define H_    8        // heads
#define D_    32       // head dim
#define M_    1024     // reduced tokens (32x32)
#define HW_   64       // spatial H=W

typedef unsigned long long u64;

// ---------------- warp-level bf16 MMA (m16n8k16) ----------------
__device__ __forceinline__ void mma16816(float* d, const uint32_t* a,
                                         const uint32_t* b) {
    asm volatile(
        "mma.sync.aligned.m16n8k16.row.col.f32.bf16.bf16.f32 "
        "{%0,%1,%2,%3}, {%4,%5,%6,%7}, {%8,%9}, {%0,%1,%2,%3};"
        : "+f"(d[0]), "+f"(d[1]), "+f"(d[2]), "+f"(d[3])
        : "r"(a[0]), "r"(a[1]), "r"(a[2]), "r"(a[3]), "r"(b[0]), "r"(b[1]));
}

__device__ __forceinline__ float ex2(float x) {
    float r; asm("ex2.approx.f32 %0, %1;" : "=f"(r) : "f"(x)); return r;
}

// ---------------- cp.async helpers ----------------
__device__ __forceinline__ uint32_t s2u(const void* p) {
    uint32_t a;
    asm("{ .reg .u64 t; cvta.to.shared.u64 t, %1; cvt.u32.u64 %0, t; }"
        : "=r"(a) : "l"(p));
    return a;
}
__device__ __forceinline__ void cpa(uint32_t d, const void* s) {
    asm volatile("cp.async.cg.shared.global [%0], [%1], 16;"
                 :: "r"(d), "l"(s));
}
#define CP_COMMIT() asm volatile("cp.async.commit_group;" ::: "memory")
#define CP_WAIT0()  asm volatile("cp.async.wait_group 0;" ::: "memory")
#define CP_WAIT1()  asm volatile("cp.async.wait_group 1;" ::: "memory")

// split pack: hi = bf16x2(x,y), lo = bf16x2(residuals)
__device__ __forceinline__ void pk_hl(float x, float y, uint32_t& hi, uint32_t& lo) {
    __nv_bfloat16 hx = __float2bfloat16_rn(x), hy = __float2bfloat16_rn(y);
    __nv_bfloat162 H; H.x = hx; H.y = hy;
    __nv_bfloat162 L;
    L.x = __float2bfloat16_rn(x - __bfloat162float(hx));
    L.y = __float2bfloat16_rn(y - __bfloat162float(hy));
    hi = *(uint32_t*)&H;
    lo = *(uint32_t*)&L;
}
__device__ __forceinline__ void st_split(__nv_bfloat16* H, __nv_bfloat16* L,
                                         size_t off, float x, float y) {
    uint32_t h, l;
    pk_hl(x, y, h, l);
    *(uint32_t*)&H[off] = h;
    *(uint32_t*)&L[off] = l;
}

// ---------------- scratch (device globals; both streams) ----------------
#define NX (B_*N_*C_)
__device__ __nv_bfloat16 g_qh [2*NX],         g_ql [2*NX];           // pre-scaled (x log2e)
__device__ float         g_xsf[2*B_*M_*C_];
__device__ __nv_bfloat16 g_xsh[2*B_*M_*C_],   g_xsl[2*B_*M_*C_];
__device__ __nv_bfloat16 g_kvh[2*B_*M_*2*C_], g_kvl[2*B_*M_*2*C_];
__device__ __nv_bfloat16 g_aoh[2*NX],         g_aol[2*NX];
__device__ __nv_bfloat16 g_wqh [C_*C_],   g_wql [C_*C_];
__device__ __nv_bfloat16 g_wkvh[2*C_*C_], g_wkvl[2*C_*C_];
__device__ __nv_bfloat16 g_wprh[C_*C_],   g_wprl[C_*C_];
__device__ __nv_bfloat16 g_wsrh[4*C_*C_], g_wsrl[4*C_*C_];

__device__ __forceinline__ void split4(__nv_bfloat16* H, __nv_bfloat16* L,
                                       const float* S, size_t i) {
    float4 v = *(const float4*)&S[i];
    uint32_t h0, l0, h1, l1;
    pk_hl(v.x, v.y, h0, l0);
    pk_hl(v.z, v.w, h1, l1);
    *(uint32_t*)&H[i]     = h0; *(uint32_t*)&H[i + 2] = h1;
    *(uint32_t*)&L[i]     = l0; *(uint32_t*)&L[i + 2] = l1;
}

// ---------------- merged weight split ----------------
__global__ __launch_bounds__(256)
void split_w(__nv_bfloat16* __restrict__ wqh,  __nv_bfloat16* __restrict__ wql,
             __nv_bfloat16* __restrict__ wkvh, __nv_bfloat16* __restrict__ wkvl,
             __nv_bfloat16* __restrict__ wprh, __nv_bfloat16* __restrict__ wprl,
             __nv_bfloat16* __restrict__ wsrh, __nv_bfloat16* __restrict__ wsrl,
             const float* __restrict__ Wq, const float* __restrict__ Wkv,
             const float* __restrict__ Wpr, const float* __restrict__ Wsr) {
    int bx = blockIdx.x;            // 512 blocks
    if (bx < 64) {
        size_t i = (size_t)bx * 1024 + threadIdx.x * 4;
        split4(wqh, wql, Wq, i);
    } else if (bx < 192) {
        size_t i = (size_t)(bx - 64) * 1024 + threadIdx.x * 4;
        split4(wkvh, wkvl, Wkv, i);
    } else if (bx < 256) {
        size_t i = (size_t)(bx - 192) * 1024 + threadIdx.x * 4;
        split4(wprh, wprl, Wpr, i);
    } else {
        size_t i = (size_t)(bx - 256) * 1024 + threadIdx.x * 4;
        split4(wsrh, wsrl, Wsr, i);
    }
}

// ================= GEMM core =================
#define GSTR 72
// gemm_s: two full buffers (A hi/lo + B hi/lo per buffer)
#define SBUF_ELEMS (2 * 128 * GSTR + 2 * 64 * GSTR)          // 27648
#define SMEM_S_BYTES (2 * SBUF_ELEMS * 2)                    // 110592
// gemm_qsr: single A buffer + double B buffer
#define QA_ELEMS (2 * 128 * GSTR)                            // 18432
#define QB_ELEMS (2 * 64 * GSTR)                             // 9216
#define SMEM_Q_BYTES ((QA_ELEMS + 2 * QB_ELEMS) * 2)         // 73728

// shared MMA inner step over one 64-k chunk (pointers select buffer)
__device__ __forceinline__ void mma_chunk(
    const __nv_bfloat16* sAh, const __nv_bfloat16* sAl,
    const __nv_bfloat16* sBh, const __nv_bfloat16* sBl,
    int wm, int wn, int fr, int fc, float acc[2][4][4]) {
#pragma unroll
    for (int ks = 0; ks < 4; ks++) {
        const int kb = ks * 16 + fc * 2;
        uint32_t Ahf[2][4], Alf[2][4], Bhf[4][2], Blf[4][2];
#pragma unroll
        for (int mt = 0; mt < 2; mt++) {
            int rbase = (wm * 32 + mt * 16 + fr) * GSTR + kb;
            Ahf[mt][0] = *(const uint32_t*)&sAh[rbase];
            Ahf[mt][1] = *(const uint32_t*)&sAh[rbase + 8 * GSTR];
            Ahf[mt][2] = *(const uint32_t*)&sAh[rbase + 8];
            Ahf[mt][3] = *(const uint32_t*)&sAh[rbase + 8 * GSTR + 8];
            Alf[mt][0] = *(const uint32_t*)&sAl[rbase];
            Alf[mt][1] = *(const uint32_t*)&sAl[rbase + 8 * GSTR];
            Alf[mt][2] = *(const uint32_t*)&sAl[rbase + 8];
            Alf[mt][3] = *(const uint32_t*)&sAl[rbase + 8 * GSTR + 8];
        }
#pragma unroll
        for (int nt = 0; nt < 4; nt++) {
            int rbase = (wn * 32 + nt * 8 + fr) * GSTR + kb;
            Bhf[nt][0] = *(const uint32_t*)&sBh[rbase];
            Bhf[nt][1] = *(const uint32_t*)&sBh[rbase + 8];
            Blf[nt][0] = *(const uint32_t*)&sBl[rbase];
            Blf[nt][1] = *(const uint32_t*)&sBl[rbase + 8];
        }
#pragma unroll
        for (int mt = 0; mt < 2; mt++)
#pragma unroll
            for (int nt = 0; nt < 4; nt++) {
                mma16816(acc[mt][nt], Ahf[mt], Bhf[nt]);
                mma16816(acc[mt][nt], Ahf[mt], Blf[nt]);
                mma16816(acc[mt][nt], Alf[mt], Bhf[nt]);
            }
    }
}

// ---- fused q-proj + SR-conv GEMM; A reg-staged w/ inline convert, B cp.async ----
// bx <  128 : SR task (K=1024, im2col gather, out f32 xsf + bsr)
// bx >= 128 : Q  task (K=256,  out split qh/ql * scale*log2e)
__global__ __launch_bounds__(256)
void gemm_qsr(const float* __restrict__ x0, const float* __restrict__ x1,
              const __nv_bfloat16* __restrict__ wqh, const __nv_bfloat16* __restrict__ wql,
              const __nv_bfloat16* __restrict__ wsrh, const __nv_bfloat16* __restrict__ wsrl,
              __nv_bfloat16* __restrict__ qhO, __nv_bfloat16* __restrict__ qlO,
              float* __restrict__ xsf, const float* __restrict__ bsr) {
    extern __shared__ __nv_bfloat16 sm[];
    __nv_bfloat16* sAh = sm;
    __nv_bfloat16* sAl = sm + 128 * GSTR;
    __nv_bfloat16* sB  = sm + QA_ELEMS;          // two B buffers follow
    const uint32_t smb = s2u(sm);

    const int bx = blockIdx.x;
    const bool issr = bx < 128;
    int z, i0, j0, K;
    const __nv_bfloat16 *Bh, *Bl;
    if (issr) {
        int tb = bx;
        z = tb >> 6;
        int r = tb & 63;
        i0 = (r >> 2) * 128; j0 = (r & 3) * 64;
        K = 1024; Bh = wsrh; Bl = wsrl;
    } else {
        int tb = bx - 128;
        z = tb >> 8;
        int r = tb & 255;
        i0 = (r >> 2) * 128; j0 = (r & 3) * 64;
        K = 256; Bh = wqh; Bl = wql;
    }
    const float* X = z ? x1 : x0;

    const int tid = threadIdx.x, wid = tid >> 5, lane = tid & 31;
    const int wm = wid & 3, wn = wid >> 2;
    const int fr = lane >> 2, fc = lane & 3;

    float acc[2][4][4] = {};
    uint32_t rAh[16], rAl[16];

    // B cp.async issue for one chunk into buffer `buf`
    const int brow = tid >> 3, bkq = (tid & 7) << 3;   // covers rows 0..31; two r-steps
    auto issueB = [&](int k0, int buf) {
        uint32_t ub = smb + (QA_ELEMS + buf * QB_ELEMS) * 2;
#pragma unroll
        for (int r = 0; r < 2; r++) {
            int row = brow + 32 * r;
            size_t gb = (size_t)(j0 + row) * K + k0 + bkq;
            cpa(ub + (row * GSTR + bkq) * 2, &Bh[gb]);
            cpa(ub + (64 * GSTR + row * GSTR + bkq) * 2, &Bl[gb]);
        }
    };
    // A register staging (convert at load)
    auto loadA = [&](int k0) {
        if (!issr) {
#pragma unroll
            for (int r = 0; r < 4; r++) {
                int f = tid + 256 * r;
                int row = f >> 3, kq = (f & 7) << 3;
                const float* ga = &X[(size_t)(i0 + row) * C_ + k0 + kq];
                float4 v0 = *(const float4*)ga;
                float4 v1 = *(const float4*)(ga + 4);
                pk_hl(v0.x, v0.y, rAh[4 * r + 0], rAl[4 * r + 0]);
                pk_hl(v0.z, v0.w, rAh[4 * r + 1], rAl[4 * r + 1]);
                pk_hl(v1.x, v1.y, rAh[4 * r + 2], rAl[4 * r + 2]);
                pk_hl(v1.z, v1.w, rAh[4 * r + 3], rAl[4 * r + 3]);
            }
        } else {
            const int cin0 = k0 >> 2;
#pragma unroll
            for (int it = 0; it < 2; it++) {
                int f = tid + 256 * it;
                int row = f >> 2;
                int qp  = (f >> 1) & 1;
                int hh  = f & 1;
                int t = i0 + row;
                int b = t >> 10, m = t & 1023;
                int i = m >> 5, j = m & 31;
                int n0 = (2 * i + qp) * HW_ + 2 * j;
                const float* p0 = &X[((size_t)b * N_ + n0) * C_ + cin0 + hh * 8];
                float4 a0 = *(const float4*)p0;
                float4 a1 = *(const float4*)(p0 + 4);
                float4 c0 = *(const float4*)(p0 + C_);
                float4 c1 = *(const float4*)(p0 + C_ + 4);
                float av[8] = {a0.x, a0.y, a0.z, a0.w, a1.x, a1.y, a1.z, a1.w};
                float cv[8] = {c0.x, c0.y, c0.z, c0.w, c1.x, c1.y, c1.z, c1.w};
#pragma unroll
                for (int c = 0; c < 8; c++)
                    pk_hl(av[c], cv[c], rAh[8 * it + c], rAl[8 * it + c]);
            }
        }
    };
    auto storeA = [&]() {
        if (!issr) {
#pragma unroll
            for (int r = 0; r < 4; r++) {
                int f = tid + 256 * r;
                int row = f >> 3, kq = (f & 7) << 3;
                *(uint4*)&sAh[row * GSTR + kq] =
                    make_uint4(rAh[4*r], rAh[4*r+1], rAh[4*r+2], rAh[4*r+3]);
                *(uint4*)&sAl[row * GSTR + kq] =
                    make_uint4(rAl[4*r], rAl[4*r+1], rAl[4*r+2], rAl[4*r+3]);
            }
        } else {
#pragma unroll
            for (int it = 0; it < 2; it++) {
                int f = tid + 256 * it;
                int row = f >> 2;
                int qp  = (f >> 1) & 1;
                int hh  = f & 1;
                int sb = row * GSTR + hh * 32 + qp * 2;
#pragma unroll
                for (int c = 0; c < 8; c++) {
                    *(uint32_t*)&sAh[sb + c * 4] = rAh[8 * it + c];
                    *(uint32_t*)&sAl[sb + c * 4] = rAl[8 * it + c];
                }
            }
        }
    };

    issueB(0, 0);
    CP_COMMIT();
    loadA(0);
    const int nch = K >> 6;
    for (int c = 0; c < nch; c++) {
        __syncthreads();                  // prior MMA done; A smem + B buf^1 free
        storeA();
        if (c + 1 < nch) { issueB((c + 1) << 6, (c + 1) & 1); CP_COMMIT(); CP_WAIT1(); }
        else CP_WAIT0();
        __syncthreads();
        if (c + 1 < nch) loadA((c + 1) << 6);   // LDG+CVT overlap MMAs
        const __nv_bfloat16* bb = sB + (c & 1) * QB_ELEMS;
        mma_chunk(sAh, sAl, bb, bb + 64 * GSTR, wm, wn, fr, fc, acc);
    }

    if (issr) {
        float* out = xsf + (size_t)z * (B_ * M_ * C_);
#pragma unroll
        for (int mt = 0; mt < 2; mt++)
#pragma unroll
            for (int nt = 0; nt < 4; nt++) {
                int col = j0 + wn * 32 + nt * 8 + fc * 2;
                float bxv = bsr[col], byv = bsr[col + 1];
                int row0 = i0 + wm * 32 + mt * 16 + fr;
                *(float2*)&out[(size_t)row0 * C_ + col] =
                    make_float2(acc[mt][nt][0] + bxv, acc[mt][nt][1] + byv);
                *(float2*)&out[(size_t)(row0 + 8) * C_ + col] =
                    make_float2(acc[mt][nt][2] + bxv, acc[mt][nt][3] + byv);
            }
    } else {
        const float sc = 0.17677669529663687f * 1.4426950408889634f;
        __nv_bfloat16* oh = qhO + (size_t)z * NX;
        __nv_bfloat16* ol = qlO + (size_t)z * NX;
#pragma unroll
        for (int mt = 0; mt < 2; mt++)
#pragma unroll
            for (int nt = 0; nt < 4; nt++) {
                int col = j0 + wn * 32 + nt * 8 + fc * 2;
                int row0 = i0 + wm * 32 + mt * 16 + fr;
                st_split(oh, ol, (size_t)row0 * C_ + col,
                         acc[mt][nt][0] * sc, acc[mt][nt][1] * sc);
                st_split(oh, ol, (size_t)(row0 + 8) * C_ + col,
                         acc[mt][nt][2] * sc, acc[mt][nt][3] * sc);
            }
    }
}

// ---- generic GEMM (kv + proj), full cp.async double buffer ----
__global__ __launch_bounds__(256)
void gemm_s(float* __restrict__ outf,
            __nv_bfloat16* __restrict__ outh, __nv_bfloat16* __restrict__ outl,
            const __nv_bfloat16* __restrict__ Ah, const __nv_bfloat16* __restrict__ Al,
            const __nv_bfloat16* __restrict__ Bh, const __nv_bfloat16* __restrict__ Bl,
            const float* __restrict__ bias, int Nc, int K,
            size_t strA, size_t strO, int splitout) {
    extern __shared__ __nv_bfloat16 sm[];
    const uint32_t smb = s2u(sm);

    const int z = blockIdx.z;
    Ah += z * strA; Al += z * strA;
    const int tid = threadIdx.x, wid = tid >> 5, lane = tid & 31;
    const int wm = wid & 3, wn = wid >> 2;
    const int fr = lane >> 2, fc = lane & 3;
    const int i0 = blockIdx.y * 128, j0 = blockIdx.x * 64;

    float acc[2][4][4] = {};

    const int arow = tid >> 3, akq = (tid & 7) << 3;     // A: 4 r-steps of 32 rows
    auto issue = [&](int k0, int buf) {
        uint32_t ub = smb + buf * SBUF_ELEMS * 2;
#pragma unroll
        for (int r = 0; r < 4; r++) {
            int row = arow + 32 * r;
            size_t ga = (size_t)(i0 + row) * K + k0 + akq;
            cpa(ub + (row * GSTR + akq) * 2, &Ah[ga]);
            cpa(ub + (128 * GSTR + row * GSTR + akq) * 2, &Al[ga]);
        }
#pragma unroll
        for (int r = 0; r < 2; r++) {
            int row = arow + 32 * r;
            size_t gb = (size_t)(j0 + row) * K + k0 + akq;
            cpa(ub + (2 * 128 * GSTR + row * GSTR + akq) * 2, &Bh[gb]);
            cpa(ub + (2 * 128 * GSTR + 64 * GSTR + row * GSTR + akq) * 2, &Bl[gb]);
        }
    };

    issue(0, 0);
    CP_COMMIT();
    const int nch = K >> 6;
    for (int c = 0; c < nch; c++) {
        if (c + 1 < nch) { issue((c + 1) << 6, (c + 1) & 1); CP_COMMIT(); CP_WAIT1(); }
        else CP_WAIT0();
        __syncthreads();                  // chunk c visible to all
        const __nv_bfloat16* bb = sm + (c & 1) * SBUF_ELEMS;
        mma_chunk(bb, bb + 128 * GSTR, bb + 2 * 128 * GSTR,
                  bb + 2 * 128 * GSTR + 64 * GSTR, wm, wn, fr, fc, acc);
        __syncthreads();                  // done reading buf c before overwrite
    }

    if (!splitout) {
        float* out = outf + z * strO;
#pragma unroll
        for (int mt = 0; mt < 2; mt++)
#pragma unroll
            for (int nt = 0; nt < 4; nt++) {
                int col = j0 + wn * 32 + nt * 8 + fc * 2;
                float bxv = 0.f, byv = 0.f;
                if (bias) { bxv = bias[col]; byv = bias[col + 1]; }
                int row0 = i0 + wm * 32 + mt * 16 + fr;
                *(float2*)&out[(size_t)row0 * Nc + col] =
                    make_float2(acc[mt][nt][0] + bxv, acc[mt][nt][1] + byv);
                *(float2*)&out[(size_t)(row0 + 8) * Nc + col] =
                    make_float2(acc[mt][nt][2] + bxv, acc[mt][nt][3] + byv);
            }
    } else {
        __nv_bfloat16* oh = outh + z * strO;
        __nv_bfloat16* ol = outl + z * strO;
#pragma unroll
        for (int mt = 0; mt < 2; mt++)
#pragma unroll
            for (int nt = 0; nt < 4; nt++) {
                int col = j0 + wn * 32 + nt * 8 + fc * 2;
                int row0 = i0 + wm * 32 + mt * 16 + fr;
                st_split(oh, ol, (size_t)row0 * Nc + col,
                         acc[mt][nt][0], acc[mt][nt][1]);
                st_split(oh, ol, (size_t)(row0 + 8) * Nc + col,
                         acc[mt][nt][2], acc[mt][nt][3]);
            }
    }
}

// ---------------- LayerNorm: warp per row, float4 IO ----------------
__global__ __launch_bounds__(256)
void layernorm_k(const float* __restrict__ xsf,
                 __nv_bfloat16* __restrict__ xsh, __nv_bfloat16* __restrict__ xsl,
                 const float* __restrict__ w0, const float* __restrict__ b0,
                 const float* __restrict__ w1, const float* __restrict__ b1) {
    int z = blockIdx.y;
    size_t zoff = (size_t)z * B_ * M_ * C_;
    const float* w = z ? w1 : w0;
    const float* bv = z ? b1 : b0;
    int row = blockIdx.x * 8 + (threadIdx.x >> 5);
    int lane = threadIdx.x & 31;
    const float* src = xsf + zoff + (size_t)row * C_ + lane * 8;
    float4 a = *(const float4*)src;
    float4 c = *(const float4*)(src + 4);
    float v[8] = {a.x, a.y, a.z, a.w, c.x, c.y, c.z, c.w};
    float s = 0.f, s2 = 0.f;
#pragma unroll
    for (int i = 0; i < 8; i++) { s += v[i]; s2 += v[i] * v[i]; }
#pragma unroll
    for (int o = 16; o > 0; o >>= 1) {
        s  += __shfl_xor_sync(~0u, s,  o);
        s2 += __shfl_xor_sync(~0u, s2, o);
    }
    float mu  = s * (1.f / C_);
    float var = s2 * (1.f / C_) - mu * mu;
    float inv = rsqrtf(var + 1e-5f);
    float4 wa = *(const float4*)&w[lane * 8];
    float4 wc = *(const float4*)&w[lane * 8 + 4];
    float4 ba = *(const float4*)&bv[lane * 8];
    float4 bc = *(const float4*)&bv[lane * 8 + 4];
    float wv[8] = {wa.x, wa.y, wa.z, wa.w, wc.x, wc.y, wc.z, wc.w};
    float bb[8] = {ba.x, ba.y, ba.z, ba.w, bc.x, bc.y, bc.z, bc.w};
    size_t o = zoff + (size_t)row * C_ + lane * 8;
#pragma unroll
    for (int i = 0; i < 4; i++) {
        float y0 = (v[2 * i]     - mu) * inv * wv[2 * i]     + bb[2 * i];
        float y1 = (v[2 * i + 1] - mu) * inv * wv[2 * i + 1] + bb[2 * i + 1];
        st_split(xsh, xsl, o + 2 * i, y0, y1);
    }
}

// ================ HMMA fused flash attention (reg-prefetch pipeline) ================
#define ASTR 40
#define VSTR 72
__global__ __launch_bounds__(256, 2)
void attention_k(__nv_bfloat16* __restrict__ aohB, __nv_bfloat16* __restrict__ aolB,
                 const __nv_bfloat16* __restrict__ qhB, const __nv_bfloat16* __restrict__ qlB,
                 const __nv_bfloat16* __restrict__ kvhB, const __nv_bfloat16* __restrict__ kvlB) {
    __shared__ __nv_bfloat16 qh[128][ASTR], ql[128][ASTR];
    __shared__ __nv_bfloat16 kh[64][ASTR],  kl[64][ASTR];
    __shared__ __nv_bfloat16 vhT[32][VSTR], vlT[32][VSTR];

    const int z = blockIdx.z;
    const size_t sQ  = (size_t)B_ * N_ * C_;
    const size_t sKV = (size_t)B_ * M_ * 2 * C_;
    const __nv_bfloat16* qgh = qhB + z * sQ;
    const __nv_bfloat16* qgl = qlB + z * sQ;
    const __nv_bfloat16* kvh = kvhB + z * sKV;
    const __nv_bfloat16* kvl = kvlB + z * sKV;
    __nv_bfloat16* aoh = aohB + z * sQ;
    __nv_bfloat16* aol = aolB + z * sQ;
    const int tid = threadIdx.x, wid = tid >> 5, lane = tid & 31;
    const int fr = lane >> 2, fc = lane & 3;
    const int bh = blockIdx.y;
    const int b = bh >> 3, h = bh & 7;
    const int r0 = blockIdx.x * 128;

    const size_t qbase = ((size_t)b * N_ + r0) * C_ + h * D_;
#pragma unroll
    for (int r = 0; r < 2; r++) {
        int idx = tid + 256 * r;
        int row = idx >> 2, kq = (idx & 3) << 3;
        *(uint4*)&qh[row][kq] = *(const uint4*)&qgh[qbase + (size_t)row * C_ + kq];
        *(uint4*)&ql[row][kq] = *(const uint4*)&qgl[qbase + (size_t)row * C_ + kq];
    }

    float m0 = -1e30f, m1 = -1e30f, l0 = 0.f, l1 = 0.f;
    float O[4][4] = {};
    const size_t kbase = (size_t)b * M_ * (2 * C_) + h * D_;

    const int kj = tid >> 2, kq4 = (tid & 3) << 3;
    const int vjp = tid >> 3, vdq = (tid & 7) << 2;
    uint4 pkh, pkl;
    uint2 pah, pch, pal, pcl;
    {
        size_t ga = kbase + (size_t)kj * (2 * C_) + kq4;
        pkh = *(const uint4*)&kvh[ga];
        pkl = *(const uint4*)&kvl[ga];
        size_t gv = kbase + (size_t)(2 * vjp) * (2 * C_) + C_ + vdq;
        pah = *(const uint2*)&kvh[gv];
        pch = *(const uint2*)&kvh[gv + 2 * C_];
        pal = *(const uint2*)&kvl[gv];
        pcl = *(const uint2*)&kvl[gv + 2 * C_];
    }

    for (int j0 = 0; j0 < M_; j0 += 64) {
        __syncthreads();
        *(uint4*)&kh[kj][kq4] = pkh;
        *(uint4*)&kl[kj][kq4] = pkl;
        *(uint32_t*)&vhT[vdq + 0][2 * vjp] = __byte_perm(pah.x, pch.x, 0x5410);
        *(uint32_t*)&vhT[vdq + 1][2 * vjp] = __byte_perm(pah.x, pch.x, 0x7632);
        *(uint32_t*)&vhT[vdq + 2][2 * vjp] = __byte_perm(pah.y, pch.y, 0x5410);
        *(uint32_t*)&vhT[vdq + 3][2 * vjp] = __byte_perm(pah.y, pch.y, 0x7632);
        *(uint32_t*)&vlT[vdq + 0][2 * vjp] = __byte_perm(pal.x, pcl.x, 0x5410);
        *(uint32_t*)&vlT[vdq + 1][2 * vjp] = __byte_perm(pal.x, pcl.x, 0x7632);
        *(uint32_t*)&vlT[vdq + 2][2 * vjp] = __byte_perm(pal.y, pcl.y, 0x5410);
        *(uint32_t*)&vlT[vdq + 3][2 * vjp] = __byte_perm(pal.y, pcl.y, 0x7632);
        __syncthreads();
        if (j0 + 64 < M_) {
            size_t ga = kbase + (size_t)(j0 + 64 + kj) * (2 * C_) + kq4;
            pkh = *(const uint4*)&kvh[ga];
            pkl = *(const uint4*)&kvl[ga];
            size_t gv = kbase + (size_t)(j0 + 64 + 2 * vjp) * (2 * C_) + C_ + vdq;
            pah = *(const uint2*)&kvh[gv];
            pch = *(const uint2*)&kvh[gv + 2 * C_];
            pal = *(const uint2*)&kvl[gv];
            pcl = *(const uint2*)&kvl[gv + 2 * C_];
        }

        float S[8][4] = {};
        const int arow = (wid << 4) + fr;
#pragma unroll
        for (int s = 0; s < 2; s++) {
            const int kb = (s << 4) + (fc << 1);
            uint32_t Ah[4], Al[4];
            Ah[0] = *(const uint32_t*)&qh[arow][kb];
            Ah[1] = *(const uint32_t*)&qh[arow + 8][kb];
            Ah[2] = *(const uint32_t*)&qh[arow][kb + 8];
            Ah[3] = *(const uint32_t*)&qh[arow + 8][kb + 8];
            Al[0] = *(const uint32_t*)&ql[arow][kb];
            Al[1] = *(const uint32_t*)&ql[arow + 8][kb];
            Al[2] = *(const uint32_t*)&ql[arow][kb + 8];
            Al[3] = *(const uint32_t*)&ql[arow + 8][kb + 8];
#pragma unroll
            for (int t = 0; t < 8; t++) {
                const int brow = (t << 3) + fr;
                uint32_t Bh[2], Bl[2];
                Bh[0] = *(const uint32_t*)&kh[brow][kb];
                Bh[1] = *(const uint32_t*)&kh[brow][kb + 8];
                Bl[0] = *(const uint32_t*)&kl[brow][kb];
                Bl[1] = *(const uint32_t*)&kl[brow][kb + 8];
                mma16816(S[t], Ah, Bh);
                mma16816(S[t], Ah, Bl);
                mma16816(S[t], Al, Bh);
            }
        }

        float cm0 = -1e30f, cm1 = -1e30f;
#pragma unroll
        for (int t = 0; t < 8; t++) {
            cm0 = fmaxf(cm0, fmaxf(S[t][0], S[t][1]));
            cm1 = fmaxf(cm1, fmaxf(S[t][2], S[t][3]));
        }
        cm0 = fmaxf(cm0, __shfl_xor_sync(~0u, cm0, 1));
        cm0 = fmaxf(cm0, __shfl_xor_sync(~0u, cm0, 2));
        cm1 = fmaxf(cm1, __shfl_xor_sync(~0u, cm1, 1));
        cm1 = fmaxf(cm1, __shfl_xor_sync(~0u, cm1, 2));
        float nm0 = fmaxf(m0, cm0), nm1 = fmaxf(m1, cm1);
        float corr0 = ex2(m0 - nm0), corr1 = ex2(m1 - nm1);
        m0 = nm0; m1 = nm1;
        float ps0 = 0.f, ps1 = 0.f;
#pragma unroll
        for (int t = 0; t < 8; t++) {
            S[t][0] = ex2(S[t][0] - nm0);
            S[t][1] = ex2(S[t][1] - nm0);
            S[t][2] = ex2(S[t][2] - nm1);
            S[t][3] = ex2(S[t][3] - nm1);
            ps0 += S[t][0] + S[t][1];
            ps1 += S[t][2] + S[t][3];
        }
        ps0 += __shfl_xor_sync(~0u, ps0, 1);
        ps0 += __shfl_xor_sync(~0u, ps0, 2);
        ps1 += __shfl_xor_sync(~0u, ps1, 1);
        ps1 += __shfl_xor_sync(~0u, ps1, 2);
        l0 = l0 * corr0 + ps0;
        l1 = l1 * corr1 + ps1;
#pragma unroll
        for (int u = 0; u < 4; u++) {
            O[u][0] *= corr0; O[u][1] *= corr0;
            O[u][2] *= corr1; O[u][3] *= corr1;
        }

#pragma unroll
        for (int s = 0; s < 4; s++) {
            uint32_t Ph[4], Pl[4];
            pk_hl(S[2 * s][0],     S[2 * s][1],     Ph[0], Pl[0]);
            pk_hl(S[2 * s][2],     S[2 * s][3],     Ph[1], Pl[1]);
            pk_hl(S[2 * s + 1][0], S[2 * s + 1][1], Ph[2], Pl[2]);
            pk_hl(S[2 * s + 1][2], S[2 * s + 1][3], Ph[3], Pl[3]);
            const int jb = (s << 4) + (fc << 1);
#pragma unroll
            for (int u = 0; u < 4; u++) {
                const int dn = (u << 3) + fr;
                uint32_t Bh[2], Bl[2];
                Bh[0] = *(const uint32_t*)&vhT[dn][jb];
                Bh[1] = *(const uint32_t*)&vhT[dn][jb + 8];
                Bl[0] = *(const uint32_t*)&vlT[dn][jb];
                Bl[1] = *(const uint32_t*)&vlT[dn][jb + 8];
                mma16816(O[u], Ph, Bh);
                mma16816(O[u], Ph, Bl);
                mma16816(O[u], Pl, Bh);
            }
        }
    }

    const float inv0 = 1.f / l0, inv1 = 1.f / l1;
    const size_t obase = ((size_t)b * N_ + r0) * C_ + h * D_;
    const int grow = (wid << 4) + fr;
#pragma unroll
    for (int u = 0; u < 4; u++) {
        int col = (u << 3) + (fc << 1);
        st_split(aoh, aol, obase + (size_t)grow * C_ + col,
                 O[u][0] * inv0, O[u][1] * inv0);
        st_split(aoh, aol, obase + (size_t)(grow + 8) * C_ + col,
                 O[u][2] * inv1, O[u][3] * inv1);
    }
}

// ---------------- launch ----------------
extern "C" void kernel_launch(void* const* d_in, const int* in_sizes, int n_in,
                              void* d_out, int out_size) {
    const float* x0     = (const float*)d_in[0];
    const float* x1     = (const float*)d_in[1];
    const float* Wq     = (const float*)d_in[2];
    const float* Wkv    = (const float*)d_in[3];
    const float* Wproj  = (const float*)d_in[4];
    const float* bproj  = (const float*)d_in[5];
    const float* Wsr    = (const float*)d_in[6];
    const float* bsr    = (const float*)d_in[7];
    const float* lnw0   = (const float*)d_in[8];
    const float* lnb0   = (const float*)d_in[9];
    const float* lnw1   = (const float*)d_in[10];
    const float* lnb1   = (const float*)d_in[11];
    float* out = (float*)d_out;

    __nv_bfloat16 *qh, *ql, *xsh, *xsl, *kvh, *kvl, *aoh, *aol;
    __nv_bfloat16 *wqh, *wql, *wkvh, *wkvl, *wprh, *wprl, *wsrh, *wsrl;
    float* xsf;
    cudaGetSymbolAddress((void**)&qh,   g_qh);   cudaGetSymbolAddress((void**)&ql,   g_ql);
    cudaGetSymbolAddress((void**)&xsf,  g_xsf);
    cudaGetSymbolAddress((void**)&xsh,  g_xsh);  cudaGetSymbolAddress((void**)&xsl,  g_xsl);
    cudaGetSymbolAddress((void**)&kvh,  g_kvh);  cudaGetSymbolAddress((void**)&kvl,  g_kvl);
    cudaGetSymbolAddress((void**)&aoh,  g_aoh);  cudaGetSymbolAddress((void**)&aol,  g_aol);
    cudaGetSymbolAddress((void**)&wqh,  g_wqh);  cudaGetSymbolAddress((void**)&wql,  g_wql);
    cudaGetSymbolAddress((void**)&wkvh, g_wkvh); cudaGetSymbolAddress((void**)&wkvl, g_wkvl);
    cudaGetSymbolAddress((void**)&wprh, g_wprh); cudaGetSymbolAddress((void**)&wprl, g_wprl);
    cudaGetSymbolAddress((void**)&wsrh, g_wsrh); cudaGetSymbolAddress((void**)&wsrl, g_wsrl);

    cudaFuncSetAttribute(gemm_s,
                         cudaFuncAttributeMaxDynamicSharedMemorySize, SMEM_S_BYTES);
    cudaFuncSetAttribute(gemm_qsr,
                         cudaFuncAttributeMaxDynamicSharedMemorySize, SMEM_Q_BYTES);

    const size_t sQ  = (size_t)NX;
    const size_t sXS = (size_t)B_ * M_ * C_;
    const size_t sKV = (size_t)B_ * M_ * 2 * C_;

    // (1) split weights (x converted inline in gemm_qsr)
    split_w<<<512, 256>>>(wqh, wql, wkvh, wkvl, wprh, wprl, wsrh, wsrl,
                          Wq, Wkv, Wproj, Wsr);
    // (2) fused q-proj + SR-conv (pipelined: A reg-staged, B cp.async)
    gemm_qsr<<<640, 256, SMEM_Q_BYTES>>>(x0, x1, wqh, wql, wsrh, wsrl,
                                         qh, ql, xsf, bsr);
    // (3) layernorm -> split (warp per row)
    layernorm_k<<<dim3((B_ * M_) / 8, 2), 256>>>(xsf, xsh, xsl,
                                                 lnw0, lnb0, lnw1, lnb1);
    // (4) kv = xs @ Wkv^T -> split (cp.async double-buffered)
    gemm_s<<<dim3((2 * C_) / 64, (B_ * M_) / 128, 2), 256, SMEM_S_BYTES>>>(
        nullptr, kvh, kvl, xsh, xsl, wkvh, wkvl, nullptr, 2 * C_, C_, sXS, sKV, 1);
    // (5) fused attention (pipelined)
    attention_k<<<dim3(N_ / 128, B_ * H_, 2), 256>>>(aoh, aol, qh, ql, kvh, kvl);
    // (6) y = ao @ Wproj^T + bproj (cp.async double-buffered)
    gemm_s<<<dim3(C_ / 64, (B_ * N_) / 128, 2), 256, SMEM_S_BYTES>>>(
        out, nullptr, nullptr, aoh, aol, wprh, wprl, bproj, C_, C_, sQ, sQ, 0);
}

// round 14
// speedup vs baseline: 1.5158x; 1.5158x over previous
#include <cuda_runtime.h>
#include <cuda_bf16.h>
#include <math.h>
#include <cstdint>

// Problem constants
#define B_    2
#define N_    4096
#define C_    256
#define H_    8        // heads
#define D_    32       // head dim
#define M_    1024     // reduced tokens (32x32)
#define HW_   64       // spatial H=W

typedef unsigned long long u64;

// ---------------- warp-level bf16 MMA (m16n8k16) ----------------
__device__ __forceinline__ void mma16816(float* d, const uint32_t* a,
                                         const uint32_t* b) {
    asm volatile(
        "mma.sync.aligned.m16n8k16.row.col.f32.bf16.bf16.f32 "
        "{%0,%1,%2,%3}, {%4,%5,%6,%7}, {%8,%9}, {%0,%1,%2,%3};"
        : "+f"(d[0]), "+f"(d[1]), "+f"(d[2]), "+f"(d[3])
        : "r"(a[0]), "r"(a[1]), "r"(a[2]), "r"(a[3]), "r"(b[0]), "r"(b[1]));
}

__device__ __forceinline__ float ex2(float x) {
    float r; asm("ex2.approx.f32 %0, %1;" : "=f"(r) : "f"(x)); return r;
}

// split pack: hi = bf16x2(x,y), lo = bf16x2(residuals)
__device__ __forceinline__ void pk_hl(float x, float y, uint32_t& hi, uint32_t& lo) {
    __nv_bfloat16 hx = __float2bfloat16_rn(x), hy = __float2bfloat16_rn(y);
    __nv_bfloat162 H; H.x = hx; H.y = hy;
    __nv_bfloat162 L;
    L.x = __float2bfloat16_rn(x - __bfloat162float(hx));
    L.y = __float2bfloat16_rn(y - __bfloat162float(hy));
    hi = *(uint32_t*)&H;
    lo = *(uint32_t*)&L;
}
__device__ __forceinline__ void st_split(__nv_bfloat16* H, __nv_bfloat16* L,
                                         size_t off, float x, float y) {
    uint32_t h, l;
    pk_hl(x, y, h, l);
    *(uint32_t*)&H[off] = h;
    *(uint32_t*)&L[off] = l;
}
// convert 8 fp32 -> hi/lo planes at element offset e (4 u32 per plane)
__device__ __forceinline__ void cv8(__nv_bfloat16* Hp, __nv_bfloat16* Lp, int e,
                                    float4 v0, float4 v1) {
    uint32_t h, l;
    pk_hl(v0.x, v0.y, h, l); *(uint32_t*)&Hp[e]     = h; *(uint32_t*)&Lp[e]     = l;
    pk_hl(v0.z, v0.w, h, l); *(uint32_t*)&Hp[e + 2] = h; *(uint32_t*)&Lp[e + 2] = l;
    pk_hl(v1.x, v1.y, h, l); *(uint32_t*)&Hp[e + 4] = h; *(uint32_t*)&Lp[e + 4] = l;
    pk_hl(v1.z, v1.w, h, l); *(uint32_t*)&Hp[e + 6] = h; *(uint32_t*)&Lp[e + 6] = l;
}

// ---------------- scratch (device globals; both streams) ----------------
#define NX (B_*N_*C_)
__device__ __nv_bfloat16 g_qh [2*NX],         g_ql [2*NX];           // pre-scaled (x log2e)
__device__ float         g_xsf[2*B_*M_*C_];
__device__ __nv_bfloat16 g_xsh[2*B_*M_*C_],   g_xsl[2*B_*M_*C_];
__device__ __nv_bfloat16 g_kvh[2*B_*M_*2*C_], g_kvl[2*B_*M_*2*C_];
__device__ __nv_bfloat16 g_aoh[2*NX],         g_aol[2*NX];
__device__ __nv_bfloat16 g_wqh [C_*C_],   g_wql [C_*C_];
__device__ __nv_bfloat16 g_wkvh[2*C_*C_], g_wkvl[2*C_*C_];
__device__ __nv_bfloat16 g_wprh[C_*C_],   g_wprl[C_*C_];
__device__ __nv_bfloat16 g_wsrh[4*C_*C_], g_wsrl[4*C_*C_];

__device__ __forceinline__ void split4(__nv_bfloat16* H, __nv_bfloat16* L,
                                       const float* S, size_t i) {
    float4 v = *(const float4*)&S[i];
    uint32_t h0, l0, h1, l1;
    pk_hl(v.x, v.y, h0, l0);
    pk_hl(v.z, v.w, h1, l1);
    *(uint32_t*)&H[i]     = h0; *(uint32_t*)&H[i + 2] = h1;
    *(uint32_t*)&L[i]     = l0; *(uint32_t*)&L[i + 2] = l1;
}

// ---------------- merged weight split ----------------
__global__ __launch_bounds__(256)
void split_w(__nv_bfloat16* __restrict__ wqh,  __nv_bfloat16* __restrict__ wql,
             __nv_bfloat16* __restrict__ wkvh, __nv_bfloat16* __restrict__ wkvl,
             __nv_bfloat16* __restrict__ wprh, __nv_bfloat16* __restrict__ wprl,
             __nv_bfloat16* __restrict__ wsrh, __nv_bfloat16* __restrict__ wsrl,
             const float* __restrict__ Wq, const float* __restrict__ Wkv,
             const float* __restrict__ Wpr, const float* __restrict__ Wsr) {
    int bx = blockIdx.x;            // 512 blocks
    if (bx < 64) {
        size_t i = (size_t)bx * 1024 + threadIdx.x * 4;
        split4(wqh, wql, Wq, i);
    } else if (bx < 192) {
        size_t i = (size_t)(bx - 64) * 1024 + threadIdx.x * 4;
        split4(wkvh, wkvl, Wkv, i);
    } else if (bx < 256) {
        size_t i = (size_t)(bx - 192) * 1024 + threadIdx.x * 4;
        split4(wprh, wprl, Wpr, i);
    } else {
        size_t i = (size_t)(bx - 256) * 1024 + threadIdx.x * 4;
        split4(wsrh, wsrl, Wsr, i);
    }
}

// ================= GEMM core pieces =================
#define GSTR 72
#define GSMEM_ELEMS (2 * 128 * GSTR + 2 * 64 * GSTR)
#define GSMEM_BYTES (GSMEM_ELEMS * 2)
// gemm_s uses BK=128 chunks with padded stride 136
#define G2 136
#define S2_ELEMS (2 * 128 * G2 + 2 * 64 * G2)      // 52224
#define S2_BYTES (S2_ELEMS * 2)                    // 104448

// ---- fused q-proj + SR-conv GEMM; A converted from fp32 x inline (R10) ----
// bx <  128 : SR task (K=1024, im2col gather, out f32 xsf + bsr)
// bx >= 128 : Q  task (K=256,  out split qh/ql * scale*log2e)
__global__ __launch_bounds__(256)
void gemm_qsr(const float* __restrict__ x0, const float* __restrict__ x1,
              const __nv_bfloat16* __restrict__ wqh, const __nv_bfloat16* __restrict__ wql,
              const __nv_bfloat16* __restrict__ wsrh, const __nv_bfloat16* __restrict__ wsrl,
              __nv_bfloat16* __restrict__ qhO, __nv_bfloat16* __restrict__ qlO,
              float* __restrict__ xsf, const float* __restrict__ bsr) {
    extern __shared__ __nv_bfloat16 sm[];
    __nv_bfloat16* sAh = sm;
    __nv_bfloat16* sAl = sm + 128 * GSTR;
    __nv_bfloat16* sBh = sm + 2 * 128 * GSTR;
    __nv_bfloat16* sBl = sm + 2 * 128 * GSTR + 64 * GSTR;

    const int bx = blockIdx.x;
    const bool issr = bx < 128;
    int z, i0, j0, K;
    const __nv_bfloat16 *Bh, *Bl;
    if (issr) {
        int tb = bx;
        z = tb >> 6;
        int r = tb & 63;
        i0 = (r >> 2) * 128; j0 = (r & 3) * 64;
        K = 1024; Bh = wsrh; Bl = wsrl;
    } else {
        int tb = bx - 128;
        z = tb >> 8;
        int r = tb & 255;
        i0 = (r >> 2) * 128; j0 = (r & 3) * 64;
        K = 256; Bh = wqh; Bl = wql;
    }
    const float* X = z ? x1 : x0;

    const int tid = threadIdx.x, wid = tid >> 5, lane = tid & 31;
    const int wm = wid & 3, wn = wid >> 2;
    const int fr = lane >> 2, fc = lane & 3;

    float acc[2][4][4] = {};

    for (int k0 = 0; k0 < K; k0 += 64) {
        if (!issr) {
#pragma unroll
            for (int r = 0; r < 4; r++) {
                int f = tid + 256 * r;
                int row = f >> 3, kq = (f & 7) << 3;
                const float* ga = &X[(size_t)(i0 + row) * C_ + k0 + kq];
                float4 v0 = *(const float4*)ga;
                float4 v1 = *(const float4*)(ga + 4);
                cv8(sAh, sAl, row * GSTR + kq, v0, v1);
            }
        } else {
            const int cin0 = k0 >> 2;
#pragma unroll
            for (int it = 0; it < 2; it++) {
                int f = tid + 256 * it;          // 512 tasks
                int row = f >> 2;                // 0..127
                int qp  = (f >> 1) & 1;          // kh
                int hh  = f & 1;                 // which 8-cin half
                int t = i0 + row;
                int b = t >> 10, m = t & 1023;
                int i = m >> 5, j = m & 31;
                int n0 = (2 * i + qp) * HW_ + 2 * j;
                const float* p0 = &X[((size_t)b * N_ + n0) * C_ + cin0 + hh * 8];
                float4 a0 = *(const float4*)p0;
                float4 a1 = *(const float4*)(p0 + 4);
                float4 c0 = *(const float4*)(p0 + C_);
                float4 c1 = *(const float4*)(p0 + C_ + 4);
                float av[8] = {a0.x, a0.y, a0.z, a0.w, a1.x, a1.y, a1.z, a1.w};
                float cv[8] = {c0.x, c0.y, c0.z, c0.w, c1.x, c1.y, c1.z, c1.w};
                int sb = row * GSTR + hh * 32 + qp * 2;   // kk = (hh*8+c)*4 + 2*qp
#pragma unroll
                for (int c = 0; c < 8; c++) {
                    uint32_t h, l;
                    pk_hl(av[c], cv[c], h, l);            // (kw0, kw1) pair
                    *(uint32_t*)&sAh[sb + c * 4] = h;
                    *(uint32_t*)&sAl[sb + c * 4] = l;
                }
            }
        }
#pragma unroll
        for (int r = 0; r < 2; r++) {
            int f = tid + 256 * r;
            int row = f >> 3, kq = (f & 7) << 3;
            size_t gb = (size_t)(j0 + row) * K + k0 + kq;
            *(uint4*)&sBh[row * GSTR + kq] = *(const uint4*)&Bh[gb];
            *(uint4*)&sBl[row * GSTR + kq] = *(const uint4*)&Bl[gb];
        }
        __syncthreads();

#pragma unroll
        for (int ks = 0; ks < 4; ks++) {
            const int kb = ks * 16 + fc * 2;
            uint32_t Ahf[2][4], Alf[2][4], Bhf[4][2], Blf[4][2];
#pragma unroll
            for (int mt = 0; mt < 2; mt++) {
                int rbase = (wm * 32 + mt * 16 + fr) * GSTR + kb;
                Ahf[mt][0] = *(const uint32_t*)&sAh[rbase];
                Ahf[mt][1] = *(const uint32_t*)&sAh[rbase + 8 * GSTR];
                Ahf[mt][2] = *(const uint32_t*)&sAh[rbase + 8];
                Ahf[mt][3] = *(const uint32_t*)&sAh[rbase + 8 * GSTR + 8];
                Alf[mt][0] = *(const uint32_t*)&sAl[rbase];
                Alf[mt][1] = *(const uint32_t*)&sAl[rbase + 8 * GSTR];
                Alf[mt][2] = *(const uint32_t*)&sAl[rbase + 8];
                Alf[mt][3] = *(const uint32_t*)&sAl[rbase + 8 * GSTR + 8];
            }
#pragma unroll
            for (int nt = 0; nt < 4; nt++) {
                int rbase = (wn * 32 + nt * 8 + fr) * GSTR + kb;
                Bhf[nt][0] = *(const uint32_t*)&sBh[rbase];
                Bhf[nt][1] = *(const uint32_t*)&sBh[rbase + 8];
                Blf[nt][0] = *(const uint32_t*)&sBl[rbase];
                Blf[nt][1] = *(const uint32_t*)&sBl[rbase + 8];
            }
#pragma unroll
            for (int mt = 0; mt < 2; mt++)
#pragma unroll
                for (int nt = 0; nt < 4; nt++) {
                    mma16816(acc[mt][nt], Ahf[mt], Bhf[nt]);
                    mma16816(acc[mt][nt], Ahf[mt], Blf[nt]);
                    mma16816(acc[mt][nt], Alf[mt], Bhf[nt]);
                }
        }
        __syncthreads();
    }

    if (issr) {
        float* out = xsf + (size_t)z * (B_ * M_ * C_);
#pragma unroll
        for (int mt = 0; mt < 2; mt++)
#pragma unroll
            for (int nt = 0; nt < 4; nt++) {
                int col = j0 + wn * 32 + nt * 8 + fc * 2;
                float bxv = bsr[col], byv = bsr[col + 1];
                int row0 = i0 + wm * 32 + mt * 16 + fr;
                *(float2*)&out[(size_t)row0 * C_ + col] =
                    make_float2(acc[mt][nt][0] + bxv, acc[mt][nt][1] + byv);
                *(float2*)&out[(size_t)(row0 + 8) * C_ + col] =
                    make_float2(acc[mt][nt][2] + bxv, acc[mt][nt][3] + byv);
            }
    } else {
        const float sc = 0.17677669529663687f * 1.4426950408889634f;
        __nv_bfloat16* oh = qhO + (size_t)z * NX;
        __nv_bfloat16* ol = qlO + (size_t)z * NX;
#pragma unroll
        for (int mt = 0; mt < 2; mt++)
#pragma unroll
            for (int nt = 0; nt < 4; nt++) {
                int col = j0 + wn * 32 + nt * 8 + fc * 2;
                int row0 = i0 + wm * 32 + mt * 16 + fr;
                st_split(oh, ol, (size_t)row0 * C_ + col,
                         acc[mt][nt][0] * sc, acc[mt][nt][1] * sc);
                st_split(oh, ol, (size_t)(row0 + 8) * C_ + col,
                         acc[mt][nt][2] * sc, acc[mt][nt][3] * sc);
            }
    }
}

// ---- generic GEMM (kv + proj), BK=128 chunks (fewer exposed fills) ----
__global__ __launch_bounds__(256)
void gemm_s(float* __restrict__ outf,
            __nv_bfloat16* __restrict__ outh, __nv_bfloat16* __restrict__ outl,
            const __nv_bfloat16* __restrict__ Ah, const __nv_bfloat16* __restrict__ Al,
            const __nv_bfloat16* __restrict__ Bh, const __nv_bfloat16* __restrict__ Bl,
            const float* __restrict__ bias, int Nc, int K,
            size_t strA, size_t strO, int splitout) {
    extern __shared__ __nv_bfloat16 sm[];
    __nv_bfloat16* sAh = sm;
    __nv_bfloat16* sAl = sm + 128 * G2;
    __nv_bfloat16* sBh = sm + 2 * 128 * G2;
    __nv_bfloat16* sBl = sm + 2 * 128 * G2 + 64 * G2;

    const int z = blockIdx.z;
    Ah += z * strA; Al += z * strA;
    const int tid = threadIdx.x, wid = tid >> 5, lane = tid & 31;
    const int wm = wid & 3, wn = wid >> 2;
    const int fr = lane >> 2, fc = lane & 3;
    const int i0 = blockIdx.y * 128, j0 = blockIdx.x * 64;

    float acc[2][4][4] = {};

    for (int k0 = 0; k0 < K; k0 += 128) {
        // A tiles: 128 rows x 128 k (hi+lo): 8 uint4 per thread per plane
#pragma unroll
        for (int r = 0; r < 8; r++) {
            int f = tid + 256 * r;
            int row = f >> 4, kq = (f & 15) << 3;
            size_t ga = (size_t)(i0 + row) * K + k0 + kq;
            *(uint4*)&sAh[row * G2 + kq] = *(const uint4*)&Ah[ga];
            *(uint4*)&sAl[row * G2 + kq] = *(const uint4*)&Al[ga];
        }
        // B tiles: 64 rows x 128 k
#pragma unroll
        for (int r = 0; r < 4; r++) {
            int f = tid + 256 * r;
            int row = f >> 4, kq = (f & 15) << 3;
            size_t gb = (size_t)(j0 + row) * K + k0 + kq;
            *(uint4*)&sBh[row * G2 + kq] = *(const uint4*)&Bh[gb];
            *(uint4*)&sBl[row * G2 + kq] = *(const uint4*)&Bl[gb];
        }
        __syncthreads();

#pragma unroll
        for (int ks = 0; ks < 8; ks++) {
            const int kb = ks * 16 + fc * 2;
            uint32_t Ahf[2][4], Alf[2][4], Bhf[4][2], Blf[4][2];
#pragma unroll
            for (int mt = 0; mt < 2; mt++) {
                int rbase = (wm * 32 + mt * 16 + fr) * G2 + kb;
                Ahf[mt][0] = *(const uint32_t*)&sAh[rbase];
                Ahf[mt][1] = *(const uint32_t*)&sAh[rbase + 8 * G2];
                Ahf[mt][2] = *(const uint32_t*)&sAh[rbase + 8];
                Ahf[mt][3] = *(const uint32_t*)&sAh[rbase + 8 * G2 + 8];
                Alf[mt][0] = *(const uint32_t*)&sAl[rbase];
                Alf[mt][1] = *(const uint32_t*)&sAl[rbase + 8 * G2];
                Alf[mt][2] = *(const uint32_t*)&sAl[rbase + 8];
                Alf[mt][3] = *(const uint32_t*)&sAl[rbase + 8 * G2 + 8];
            }
#pragma unroll
            for (int nt = 0; nt < 4; nt++) {
                int rbase = (wn * 32 + nt * 8 + fr) * G2 + kb;
                Bhf[nt][0] = *(const uint32_t*)&sBh[rbase];
                Bhf[nt][1] = *(const uint32_t*)&sBh[rbase + 8];
                Blf[nt][0] = *(const uint32_t*)&sBl[rbase];
                Blf[nt][1] = *(const uint32_t*)&sBl[rbase + 8];
            }
#pragma unroll
            for (int mt = 0; mt < 2; mt++)
#pragma unroll
                for (int nt = 0; nt < 4; nt++) {
                    mma16816(acc[mt][nt], Ahf[mt], Bhf[nt]);
                    mma16816(acc[mt][nt], Ahf[mt], Blf[nt]);
                    mma16816(acc[mt][nt], Alf[mt], Bhf[nt]);
                }
        }
        __syncthreads();
    }

    if (!splitout) {
        float* out = outf + z * strO;
#pragma unroll
        for (int mt = 0; mt < 2; mt++)
#pragma unroll
            for (int nt = 0; nt < 4; nt++) {
                int col = j0 + wn * 32 + nt * 8 + fc * 2;
                float bxv = 0.f, byv = 0.f;
                if (bias) { bxv = bias[col]; byv = bias[col + 1]; }
                int row0 = i0 + wm * 32 + mt * 16 + fr;
                *(float2*)&out[(size_t)row0 * Nc + col] =
                    make_float2(acc[mt][nt][0] + bxv, acc[mt][nt][1] + byv);
                *(float2*)&out[(size_t)(row0 + 8) * Nc + col] =
                    make_float2(acc[mt][nt][2] + bxv, acc[mt][nt][3] + byv);
            }
    } else {
        __nv_bfloat16* oh = outh + z * strO;
        __nv_bfloat16* ol = outl + z * strO;
#pragma unroll
        for (int mt = 0; mt < 2; mt++)
#pragma unroll
            for (int nt = 0; nt < 4; nt++) {
                int col = j0 + wn * 32 + nt * 8 + fc * 2;
                int row0 = i0 + wm * 32 + mt * 16 + fr;
                st_split(oh, ol, (size_t)row0 * Nc + col,
                         acc[mt][nt][0], acc[mt][nt][1]);
                st_split(oh, ol, (size_t)(row0 + 8) * Nc + col,
                         acc[mt][nt][2], acc[mt][nt][3]);
            }
    }
}

// ---------------- LayerNorm: warp per row, float4 IO ----------------
__global__ __launch_bounds__(256)
void layernorm_k(const float* __restrict__ xsf,
                 __nv_bfloat16* __restrict__ xsh, __nv_bfloat16* __restrict__ xsl,
                 const float* __restrict__ w0, const float* __restrict__ b0,
                 const float* __restrict__ w1, const float* __restrict__ b1) {
    int z = blockIdx.y;
    size_t zoff = (size_t)z * B_ * M_ * C_;
    const float* w = z ? w1 : w0;
    const float* bv = z ? b1 : b0;
    int row = blockIdx.x * 8 + (threadIdx.x >> 5);
    int lane = threadIdx.x & 31;
    const float* src = xsf + zoff + (size_t)row * C_ + lane * 8;
    float4 a = *(const float4*)src;
    float4 c = *(const float4*)(src + 4);
    float v[8] = {a.x, a.y, a.z, a.w, c.x, c.y, c.z, c.w};
    float s = 0.f, s2 = 0.f;
#pragma unroll
    for (int i = 0; i < 8; i++) { s += v[i]; s2 += v[i] * v[i]; }
#pragma unroll
    for (int o = 16; o > 0; o >>= 1) {
        s  += __shfl_xor_sync(~0u, s,  o);
        s2 += __shfl_xor_sync(~0u, s2, o);
    }
    float mu  = s * (1.f / C_);
    float var = s2 * (1.f / C_) - mu * mu;
    float inv = rsqrtf(var + 1e-5f);
    float4 wa = *(const float4*)&w[lane * 8];
    float4 wc = *(const float4*)&w[lane * 8 + 4];
    float4 ba = *(const float4*)&bv[lane * 8];
    float4 bc = *(const float4*)&bv[lane * 8 + 4];
    float wv[8] = {wa.x, wa.y, wa.z, wa.w, wc.x, wc.y, wc.z, wc.w};
    float bb[8] = {ba.x, ba.y, ba.z, ba.w, bc.x, bc.y, bc.z, bc.w};
    size_t o = zoff + (size_t)row * C_ + lane * 8;
#pragma unroll
    for (int i = 0; i < 4; i++) {
        float y0 = (v[2 * i]     - mu) * inv * wv[2 * i]     + bb[2 * i];
        float y1 = (v[2 * i + 1] - mu) * inv * wv[2 * i + 1] + bb[2 * i + 1];
        st_split(xsh, xsl, o + 2 * i, y0, y1);
    }
}

// ================ HMMA fused flash attention (reg-prefetch pipeline, R10) ================
#define ASTR 40
#define VSTR 72
__global__ __launch_bounds__(256, 2)
void attention_k(__nv_bfloat16* __restrict__ aohB, __nv_bfloat16* __restrict__ aolB,
                 const __nv_bfloat16* __restrict__ qhB, const __nv_bfloat16* __restrict__ qlB,
                 const __nv_bfloat16* __restrict__ kvhB, const __nv_bfloat16* __restrict__ kvlB) {
    __shared__ __nv_bfloat16 qh[128][ASTR], ql[128][ASTR];
    __shared__ __nv_bfloat16 kh[64][ASTR],  kl[64][ASTR];
    __shared__ __nv_bfloat16 vhT[32][VSTR], vlT[32][VSTR];

    const int z = blockIdx.z;
    const size_t sQ  = (size_t)B_ * N_ * C_;
    const size_t sKV = (size_t)B_ * M_ * 2 * C_;
    const __nv_bfloat16* qgh = qhB + z * sQ;
    const __nv_bfloat16* qgl = qlB + z * sQ;
    const __nv_bfloat16* kvh = kvhB + z * sKV;
    const __nv_bfloat16* kvl = kvlB + z * sKV;
    __nv_bfloat16* aoh = aohB + z * sQ;
    __nv_bfloat16* aol = aolB + z * sQ;
    const int tid = threadIdx.x, wid = tid >> 5, lane = tid & 31;
    const int fr = lane >> 2, fc = lane & 3;
    const int bh = blockIdx.y;
    const int b = bh >> 3, h = bh & 7;
    const int r0 = blockIdx.x * 128;

    const size_t qbase = ((size_t)b * N_ + r0) * C_ + h * D_;
#pragma unroll
    for (int r = 0; r < 2; r++) {
        int idx = tid + 256 * r;
        int row = idx >> 2, kq = (idx & 3) << 3;
        *(uint4*)&qh[row][kq] = *(const uint4*)&qgh[qbase + (size_t)row * C_ + kq];
        *(uint4*)&ql[row][kq] = *(const uint4*)&qgl[qbase + (size_t)row * C_ + kq];
    }

    float m0 = -1e30f, m1 = -1e30f, l0 = 0.f, l1 = 0.f;
    float O[4][4] = {};
    const size_t kbase = (size_t)b * M_ * (2 * C_) + h * D_;

    const int kj = tid >> 2, kq4 = (tid & 3) << 3;
    const int vjp = tid >> 3, vdq = (tid & 7) << 2;
    uint4 pkh, pkl;
    uint2 pah, pch, pal, pcl;
    {
        size_t ga = kbase + (size_t)kj * (2 * C_) + kq4;
        pkh = *(const uint4*)&kvh[ga];
        pkl = *(const uint4*)&kvl[ga];
        size_t gv = kbase + (size_t)(2 * vjp) * (2 * C_) + C_ + vdq;
        pah = *(const uint2*)&kvh[gv];
        pch = *(const uint2*)&kvh[gv + 2 * C_];
        pal = *(const uint2*)&kvl[gv];
        pcl = *(const uint2*)&kvl[gv + 2 * C_];
    }

    for (int j0 = 0; j0 < M_; j0 += 64) {
        __syncthreads();
        *(uint4*)&kh[kj][kq4] = pkh;
        *(uint4*)&kl[kj][kq4] = pkl;
        *(uint32_t*)&vhT[vdq + 0][2 * vjp] = __byte_perm(pah.x, pch.x, 0x5410);
        *(uint32_t*)&vhT[vdq + 1][2 * vjp] = __byte_perm(pah.x, pch.x, 0x7632);
        *(uint32_t*)&vhT[vdq + 2][2 * vjp] = __byte_perm(pah.y, pch.y, 0x5410);
        *(uint32_t*)&vhT[vdq + 3][2 * vjp] = __byte_perm(pah.y, pch.y, 0x7632);
        *(uint32_t*)&vlT[vdq + 0][2 * vjp] = __byte_perm(pal.x, pcl.x, 0x5410);
        *(uint32_t*)&vlT[vdq + 1][2 * vjp] = __byte_perm(pal.x, pcl.x, 0x7632);
        *(uint32_t*)&vlT[vdq + 2][2 * vjp] = __byte_perm(pal.y, pcl.y, 0x5410);
        *(uint32_t*)&vlT[vdq + 3][2 * vjp] = __byte_perm(pal.y, pcl.y, 0x7632);
        __syncthreads();
        if (j0 + 64 < M_) {
            size_t ga = kbase + (size_t)(j0 + 64 + kj) * (2 * C_) + kq4;
            pkh = *(const uint4*)&kvh[ga];
            pkl = *(const uint4*)&kvl[ga];
            size_t gv = kbase + (size_t)(j0 + 64 + 2 * vjp) * (2 * C_) + C_ + vdq;
            pah = *(const uint2*)&kvh[gv];
            pch = *(const uint2*)&kvh[gv + 2 * C_];
            pal = *(const uint2*)&kvl[gv];
            pcl = *(const uint2*)&kvl[gv + 2 * C_];
        }

        float S[8][4] = {};
        const int arow = (wid << 4) + fr;
#pragma unroll
        for (int s = 0; s < 2; s++) {
            const int kb = (s << 4) + (fc << 1);
            uint32_t Ah[4], Al[4];
            Ah[0] = *(const uint32_t*)&qh[arow][kb];
            Ah[1] = *(const uint32_t*)&qh[arow + 8][kb];
            Ah[2] = *(const uint32_t*)&qh[arow][kb + 8];
            Ah[3] = *(const uint32_t*)&qh[arow + 8][kb + 8];
            Al[0] = *(const uint32_t*)&ql[arow][kb];
            Al[1] = *(const uint32_t*)&ql[arow + 8][kb];
            Al[2] = *(const uint32_t*)&ql[arow][kb + 8];
            Al[3] = *(const uint32_t*)&ql[arow + 8][kb + 8];
#pragma unroll
            for (int t = 0; t < 8; t++) {
                const int brow = (t << 3) + fr;
                uint32_t Bh[2], Bl[2];
                Bh[0] = *(const uint32_t*)&kh[brow][kb];
                Bh[1] = *(const uint32_t*)&kh[brow][kb + 8];
                Bl[0] = *(const uint32_t*)&kl[brow][kb];
                Bl[1] = *(const uint32_t*)&kl[brow][kb + 8];
                mma16816(S[t], Ah, Bh);
                mma16816(S[t], Ah, Bl);
                mma16816(S[t], Al, Bh);
            }
        }

        float cm0 = -1e30f, cm1 = -1e30f;
#pragma unroll
        for (int t = 0; t < 8; t++) {
            cm0 = fmaxf(cm0, fmaxf(S[t][0], S[t][1]));
            cm1 = fmaxf(cm1, fmaxf(S[t][2], S[t][3]));
        }
        cm0 = fmaxf(cm0, __shfl_xor_sync(~0u, cm0, 1));
        cm0 = fmaxf(cm0, __shfl_xor_sync(~0u, cm0, 2));
        cm1 = fmaxf(cm1, __shfl_xor_sync(~0u, cm1, 1));
        cm1 = fmaxf(cm1, __shfl_xor_sync(~0u, cm1, 2));
        float nm0 = fmaxf(m0, cm0), nm1 = fmaxf(m1, cm1);
        float corr0 = ex2(m0 - nm0), corr1 = ex2(m1 - nm1);
        m0 = nm0; m1 = nm1;
        float ps0 = 0.f, ps1 = 0.f;
#pragma unroll
        for (int t = 0; t < 8; t++) {
            S[t][0] = ex2(S[t][0] - nm0);
            S[t][1] = ex2(S[t][1] - nm0);
            S[t][2] = ex2(S[t][2] - nm1);
            S[t][3] = ex2(S[t][3] - nm1);
            ps0 += S[t][0] + S[t][1];
            ps1 += S[t][2] + S[t][3];
        }
        ps0 += __shfl_xor_sync(~0u, ps0, 1);
        ps0 += __shfl_xor_sync(~0u, ps0, 2);
        ps1 += __shfl_xor_sync(~0u, ps1, 1);
        ps1 += __shfl_xor_sync(~0u, ps1, 2);
        l0 = l0 * corr0 + ps0;
        l1 = l1 * corr1 + ps1;
#pragma unroll
        for (int u = 0; u < 4; u++) {
            O[u][0] *= corr0; O[u][1] *= corr0;
            O[u][2] *= corr1; O[u][3] *= corr1;
        }

#pragma unroll
        for (int s = 0; s < 4; s++) {
            uint32_t Ph[4], Pl[4];
            pk_hl(S[2 * s][0],     S[2 * s][1],     Ph[0], Pl[0]);
            pk_hl(S[2 * s][2],     S[2 * s][3],     Ph[1], Pl[1]);
            pk_hl(S[2 * s + 1][0], S[2 * s + 1][1], Ph[2], Pl[2]);
            pk_hl(S[2 * s + 1][2], S[2 * s + 1][3], Ph[3], Pl[3]);
            const int jb = (s << 4) + (fc << 1);
#pragma unroll
            for (int u = 0; u < 4; u++) {
                const int dn = (u << 3) + fr;
                uint32_t Bh[2], Bl[2];
                Bh[0] = *(const uint32_t*)&vhT[dn][jb];
                Bh[1] = *(const uint32_t*)&vhT[dn][jb + 8];
                Bl[0] = *(const uint32_t*)&vlT[dn][jb];
                Bl[1] = *(const uint32_t*)&vlT[dn][jb + 8];
                mma16816(O[u], Ph, Bh);
                mma16816(O[u], Ph, Bl);
                mma16816(O[u], Pl, Bh);
            }
        }
    }

    const float inv0 = 1.f / l0, inv1 = 1.f / l1;
    const size_t obase = ((size_t)b * N_ + r0) * C_ + h * D_;
    const int grow = (wid << 4) + fr;
#pragma unroll
    for (int u = 0; u < 4; u++) {
        int col = (u << 3) + (fc << 1);
        st_split(aoh, aol, obase + (size_t)grow * C_ + col,
                 O[u][0] * inv0, O[u][1] * inv0);
        st_split(aoh, aol, obase + (size_t)(grow + 8) * C_ + col,
                 O[u][2] * inv1, O[u][3] * inv1);
    }
}

// ---------------- launch ----------------
extern "C" void kernel_launch(void* const* d_in, const int* in_sizes, int n_in,
                              void* d_out, int out_size) {
    const float* x0     = (const float*)d_in[0];
    const float* x1     = (const float*)d_in[1];
    const float* Wq     = (const float*)d_in[2];
    const float* Wkv    = (const float*)d_in[3];
    const float* Wproj  = (const float*)d_in[4];
    const float* bproj  = (const float*)d_in[5];
    const float* Wsr    = (const float*)d_in[6];
    const float* bsr    = (const float*)d_in[7];
    const float* lnw0   = (const float*)d_in[8];
    const float* lnb0   = (const float*)d_in[9];
    const float* lnw1   = (const float*)d_in[10];
    const float* lnb1   = (const float*)d_in[11];
    float* out = (float*)d_out;

    __nv_bfloat16 *qh, *ql, *xsh, *xsl, *kvh, *kvl, *aoh, *aol;
    __nv_bfloat16 *wqh, *wql, *wkvh, *wkvl, *wprh, *wprl, *wsrh, *wsrl;
    float* xsf;
    cudaGetSymbolAddress((void**)&qh,   g_qh);   cudaGetSymbolAddress((void**)&ql,   g_ql);
    cudaGetSymbolAddress((void**)&xsf,  g_xsf);
    cudaGetSymbolAddress((void**)&xsh,  g_xsh);  cudaGetSymbolAddress((void**)&xsl,  g_xsl);
    cudaGetSymbolAddress((void**)&kvh,  g_kvh);  cudaGetSymbolAddress((void**)&kvl,  g_kvl);
    cudaGetSymbolAddress((void**)&aoh,  g_aoh);  cudaGetSymbolAddress((void**)&aol,  g_aol);
    cudaGetSymbolAddress((void**)&wqh,  g_wqh);  cudaGetSymbolAddress((void**)&wql,  g_wql);
    cudaGetSymbolAddress((void**)&wkvh, g_wkvh); cudaGetSymbolAddress((void**)&wkvl, g_wkvl);
    cudaGetSymbolAddress((void**)&wprh, g_wprh); cudaGetSymbolAddress((void**)&wprl, g_wprl);
    cudaGetSymbolAddress((void**)&wsrh, g_wsrh); cudaGetSymbolAddress((void**)&wsrl, g_wsrl);

    cudaFuncSetAttribute(gemm_s,
                         cudaFuncAttributeMaxDynamicSharedMemorySize, S2_BYTES);
    cudaFuncSetAttribute(gemm_qsr,
                         cudaFuncAttributeMaxDynamicSharedMemorySize, GSMEM_BYTES);

    const size_t sQ  = (size_t)NX;
    const size_t sXS = (size_t)B_ * M_ * C_;
    const size_t sKV = (size_t)B_ * M_ * 2 * C_;

    // (1) split weights (x converted inline in gemm_qsr)
    split_w<<<512, 256>>>(wqh, wql, wkvh, wkvl, wprh, wprl, wsrh, wsrl,
                          Wq, Wkv, Wproj, Wsr);
    // (2) fused q-proj + SR-conv (im2col + fp32->split inline)
    gemm_qsr<<<640, 256, GSMEM_BYTES>>>(x0, x1, wqh, wql, wsrh, wsrl,
                                        qh, ql, xsf, bsr);
    // (3) layernorm -> split (warp per row)
    layernorm_k<<<dim3((B_ * M_) / 8, 2), 256>>>(xsf, xsh, xsl,
                                                 lnw0, lnb0, lnw1, lnb1);
    // (4) kv = xs @ Wkv^T -> split (BK=128)
    gemm_s<<<dim3((2 * C_) / 64, (B_ * M_) / 128, 2), 256, S2_BYTES>>>(
        nullptr, kvh, kvl, xsh, xsl, wkvh, wkvl, nullptr, 2 * C_, C_, sXS, sKV, 1);
    // (5) fused attention (pipelined)
    attention_k<<<dim3(N_ / 128, B_ * H_, 2), 256>>>(aoh, aol, qh, ql, kvh, kvl);
    // (6) y = ao @ Wproj^T + bproj (BK=128)
    gemm_s<<<dim3(C_ / 64, (B_ * N_) / 128, 2), 256, S2_BYTES>>>(
        out, nullptr, nullptr, aoh, aol, wprh, wprl, bproj, C_, C_, sQ, sQ, 0);
}

// round 15
// speedup vs baseline: 1.5911x; 1.0497x over previous
#include <cuda_runtime.h>
#include <cuda_bf16.h>
#include <math.h>
#include <cstdint>

// Problem constants
#define B_    2
#define N_    4096
#define C_    256
#define H_    8        // heads
#define D_    32       // head dim
#define M_    1024     // reduced tokens (32x32)
#define HW_   64       // spatial H=W

typedef unsigned long long u64;

// ---------------- warp-level bf16 MMA (m16n8k16) ----------------
__device__ __forceinline__ void mma16816(float* d, const uint32_t* a,
                                         const uint32_t* b) {
    asm volatile(
        "mma.sync.aligned.m16n8k16.row.col.f32.bf16.bf16.f32 "
        "{%0,%1,%2,%3}, {%4,%5,%6,%7}, {%8,%9}, {%0,%1,%2,%3};"
        : "+f"(d[0]), "+f"(d[1]), "+f"(d[2]), "+f"(d[3])
        : "r"(a[0]), "r"(a[1]), "r"(a[2]), "r"(a[3]), "r"(b[0]), "r"(b[1]));
}

__device__ __forceinline__ void ldm4(uint32_t* r, uint32_t a) {
    asm volatile("ldmatrix.sync.aligned.m8n8.x4.shared.b16 {%0,%1,%2,%3}, [%4];"
        : "=r"(r[0]), "=r"(r[1]), "=r"(r[2]), "=r"(r[3]) : "r"(a));
}

__device__ __forceinline__ float ex2(float x) {
    float r; asm("ex2.approx.f32 %0, %1;" : "=f"(r) : "f"(x)); return r;
}

__device__ __forceinline__ uint32_t s2u(const void* p) {
    uint32_t a;
    asm("{ .reg .u64 t; cvta.to.shared.u64 t, %1; cvt.u32.u64 %0, t; }"
        : "=r"(a) : "l"(p));
    return a;
}

// split pack: hi = bf16x2(x,y), lo = bf16x2(residuals)
__device__ __forceinline__ void pk_hl(float x, float y, uint32_t& hi, uint32_t& lo) {
    __nv_bfloat16 hx = __float2bfloat16_rn(x), hy = __float2bfloat16_rn(y);
    __nv_bfloat162 H; H.x = hx; H.y = hy;
    __nv_bfloat162 L;
    L.x = __float2bfloat16_rn(x - __bfloat162float(hx));
    L.y = __float2bfloat16_rn(y - __bfloat162float(hy));
    hi = *(uint32_t*)&H;
    lo = *(uint32_t*)&L;
}
__device__ __forceinline__ void st_split(__nv_bfloat16* H, __nv_bfloat16* L,
                                         size_t off, float x, float y) {
    uint32_t h, l;
    pk_hl(x, y, h, l);
    *(uint32_t*)&H[off] = h;
    *(uint32_t*)&L[off] = l;
}
// convert 8 fp32 -> hi/lo planes at element offset e (4 u32 per plane)
__device__ __forceinline__ void cv8(__nv_bfloat16* Hp, __nv_bfloat16* Lp, int e,
                                    float4 v0, float4 v1) {
    uint32_t h, l;
    pk_hl(v0.x, v0.y, h, l); *(uint32_t*)&Hp[e]     = h; *(uint32_t*)&Lp[e]     = l;
    pk_hl(v0.z, v0.w, h, l); *(uint32_t*)&Hp[e + 2] = h; *(uint32_t*)&Lp[e + 2] = l;
    pk_hl(v1.x, v1.y, h, l); *(uint32_t*)&Hp[e + 4] = h; *(uint32_t*)&Lp[e + 4] = l;
    pk_hl(v1.z, v1.w, h, l); *(uint32_t*)&Hp[e + 6] = h; *(uint32_t*)&Lp[e + 6] = l;
}

// ---------------- scratch (device globals; both streams) ----------------
#define NX (B_*N_*C_)
__device__ __nv_bfloat16 g_qh [2*NX],         g_ql [2*NX];           // pre-scaled (x log2e)
__device__ float         g_xsf[2*B_*M_*C_];
__device__ __nv_bfloat16 g_xsh[2*B_*M_*C_],   g_xsl[2*B_*M_*C_];
__device__ __nv_bfloat16 g_kvh[2*B_*M_*2*C_], g_kvl[2*B_*M_*2*C_];
__device__ __nv_bfloat16 g_aoh[2*NX],         g_aol[2*NX];
__device__ __nv_bfloat16 g_wqh [C_*C_],   g_wql [C_*C_];
__device__ __nv_bfloat16 g_wkvh[2*C_*C_], g_wkvl[2*C_*C_];
__device__ __nv_bfloat16 g_wprh[C_*C_],   g_wprl[C_*C_];
__device__ __nv_bfloat16 g_wsrh[4*C_*C_], g_wsrl[4*C_*C_];

__device__ __forceinline__ void split4(__nv_bfloat16* H, __nv_bfloat16* L,
                                       const float* S, size_t i) {
    float4 v = *(const float4*)&S[i];
    uint32_t h0, l0, h1, l1;
    pk_hl(v.x, v.y, h0, l0);
    pk_hl(v.z, v.w, h1, l1);
    *(uint32_t*)&H[i]     = h0; *(uint32_t*)&H[i + 2] = h1;
    *(uint32_t*)&L[i]     = l0; *(uint32_t*)&L[i + 2] = l1;
}

// ---------------- merged weight split ----------------
__global__ __launch_bounds__(256)
void split_w(__nv_bfloat16* __restrict__ wqh,  __nv_bfloat16* __restrict__ wql,
             __nv_bfloat16* __restrict__ wkvh, __nv_bfloat16* __restrict__ wkvl,
             __nv_bfloat16* __restrict__ wprh, __nv_bfloat16* __restrict__ wprl,
             __nv_bfloat16* __restrict__ wsrh, __nv_bfloat16* __restrict__ wsrl,
             const float* __restrict__ Wq, const float* __restrict__ Wkv,
             const float* __restrict__ Wpr, const float* __restrict__ Wsr) {
    int bx = blockIdx.x;            // 512 blocks
    if (bx < 64) {
        size_t i = (size_t)bx * 1024 + threadIdx.x * 4;
        split4(wqh, wql, Wq, i);
    } else if (bx < 192) {
        size_t i = (size_t)(bx - 64) * 1024 + threadIdx.x * 4;
        split4(wkvh, wkvl, Wkv, i);
    } else if (bx < 256) {
        size_t i = (size_t)(bx - 192) * 1024 + threadIdx.x * 4;
        split4(wprh, wprl, Wpr, i);
    } else {
        size_t i = (size_t)(bx - 256) * 1024 + threadIdx.x * 4;
        split4(wsrh, wsrl, Wsr, i);
    }
}

// ================= GEMM core pieces =================
#define GSTR 72
#define GSMEM_ELEMS (2 * 128 * GSTR + 2 * 64 * GSTR)
#define GSMEM_BYTES (GSMEM_ELEMS * 2)

// ldmatrix-based inner step over one 64-k chunk.
// Thread-specific base addresses (bytes): aAh/aAl point at the thread's
// A-fragment tile rows for mt=0 (mt=1 at +16*GSTR*2); aBh/aBl at nt-pair 0.
__device__ __forceinline__ void mma_chunk_lm(
    uint32_t aAh, uint32_t aAl, uint32_t aBh, uint32_t aBl,
    float acc[2][4][4]) {
#pragma unroll
    for (int ks = 0; ks < 4; ks++) {
        const uint32_t kb2 = ks * 32;   // 16 bf16 = 32 bytes
        uint32_t Ahf[2][4], Alf[2][4], Bhp[2][4], Blp[2][4];
        ldm4(Ahf[0], aAh + kb2);
        ldm4(Ahf[1], aAh + 16 * GSTR * 2 + kb2);
        ldm4(Alf[0], aAl + kb2);
        ldm4(Alf[1], aAl + 16 * GSTR * 2 + kb2);
        ldm4(Bhp[0], aBh + kb2);                     // nt0, nt1
        ldm4(Bhp[1], aBh + 16 * GSTR * 2 + kb2);     // nt2, nt3
        ldm4(Blp[0], aBl + kb2);
        ldm4(Blp[1], aBl + 16 * GSTR * 2 + kb2);
#pragma unroll
        for (int mt = 0; mt < 2; mt++)
#pragma unroll
            for (int nt = 0; nt < 4; nt++) {
                const uint32_t* bh = &Bhp[nt >> 1][(nt & 1) * 2];
                const uint32_t* bl = &Blp[nt >> 1][(nt & 1) * 2];
                mma16816(acc[mt][nt], Ahf[mt], bh);
                mma16816(acc[mt][nt], Ahf[mt], bl);
                mma16816(acc[mt][nt], Alf[mt], bh);
            }
    }
}

// Per-thread ldmatrix base addresses for the standard GSTR layout
// (sAh@0, sAl@128*GSTR, sBh@2*128*GSTR, sBl@+64*GSTR), in bytes.
__device__ __forceinline__ void lm_addrs(uint32_t smb, int lane, int wm, int wn,
                                         uint32_t& aAh, uint32_t& aAl,
                                         uint32_t& aBh, uint32_t& aBl) {
    int rowA = wm * 32 + ((lane >> 3) & 1) * 8 + (lane & 7);
    int colA = (lane >> 4) * 8;
    aAh = smb + (uint32_t)(rowA * GSTR + colA) * 2;
    aAl = aAh + 128 * GSTR * 2;
    int rowB = wn * 32 + ((lane >> 4) & 1) * 8 + (lane & 7);
    int colB = ((lane >> 3) & 1) * 8;
    aBh = smb + (uint32_t)(2 * 128 * GSTR + rowB * GSTR + colB) * 2;
    aBl = aBh + 64 * GSTR * 2;
}

// ---- fused q-proj + SR-conv GEMM; A converted from fp32 x inline ----
// bx <  128 : SR task (K=1024, im2col gather, out f32 xsf + bsr)
// bx >= 128 : Q  task (K=256,  out split qh/ql * scale*log2e)
__global__ __launch_bounds__(256)
void gemm_qsr(const float* __restrict__ x0, const float* __restrict__ x1,
              const __nv_bfloat16* __restrict__ wqh, const __nv_bfloat16* __restrict__ wql,
              const __nv_bfloat16* __restrict__ wsrh, const __nv_bfloat16* __restrict__ wsrl,
              __nv_bfloat16* __restrict__ qhO, __nv_bfloat16* __restrict__ qlO,
              float* __restrict__ xsf, const float* __restrict__ bsr) {
    extern __shared__ __nv_bfloat16 sm[];
    __nv_bfloat16* sAh = sm;
    __nv_bfloat16* sAl = sm + 128 * GSTR;
    __nv_bfloat16* sBh = sm + 2 * 128 * GSTR;
    __nv_bfloat16* sBl = sm + 2 * 128 * GSTR + 64 * GSTR;

    const int bx = blockIdx.x;
    const bool issr = bx < 128;
    int z, i0, j0, K;
    const __nv_bfloat16 *Bh, *Bl;
    if (issr) {
        int tb = bx;
        z = tb >> 6;
        int r = tb & 63;
        i0 = (r >> 2) * 128; j0 = (r & 3) * 64;
        K = 1024; Bh = wsrh; Bl = wsrl;
    } else {
        int tb = bx - 128;
        z = tb >> 8;
        int r = tb & 255;
        i0 = (r >> 2) * 128; j0 = (r & 3) * 64;
        K = 256; Bh = wqh; Bl = wql;
    }
    const float* X = z ? x1 : x0;

    const int tid = threadIdx.x, wid = tid >> 5, lane = tid & 31;
    const int wm = wid & 3, wn = wid >> 2;
    const int fr = lane >> 2, fc = lane & 3;

    uint32_t aAh, aAl, aBh, aBl;
    lm_addrs(s2u(sm), lane, wm, wn, aAh, aAl, aBh, aBl);

    float acc[2][4][4] = {};

    for (int k0 = 0; k0 < K; k0 += 64) {
        if (!issr) {
#pragma unroll
            for (int r = 0; r < 4; r++) {
                int f = tid + 256 * r;
                int row = f >> 3, kq = (f & 7) << 3;
                const float* ga = &X[(size_t)(i0 + row) * C_ + k0 + kq];
                float4 v0 = *(const float4*)ga;
                float4 v1 = *(const float4*)(ga + 4);
                cv8(sAh, sAl, row * GSTR + kq, v0, v1);
            }
        } else {
            const int cin0 = k0 >> 2;
#pragma unroll
            for (int it = 0; it < 2; it++) {
                int f = tid + 256 * it;          // 512 tasks
                int row = f >> 2;                // 0..127
                int qp  = (f >> 1) & 1;          // kh
                int hh  = f & 1;                 // which 8-cin half
                int t = i0 + row;
                int b = t >> 10, m = t & 1023;
                int i = m >> 5, j = m & 31;
                int n0 = (2 * i + qp) * HW_ + 2 * j;
                const float* p0 = &X[((size_t)b * N_ + n0) * C_ + cin0 + hh * 8];
                float4 a0 = *(const float4*)p0;
                float4 a1 = *(const float4*)(p0 + 4);
                float4 c0 = *(const float4*)(p0 + C_);
                float4 c1 = *(const float4*)(p0 + C_ + 4);
                float av[8] = {a0.x, a0.y, a0.z, a0.w, a1.x, a1.y, a1.z, a1.w};
                float cv[8] = {c0.x, c0.y, c0.z, c0.w, c1.x, c1.y, c1.z, c1.w};
                int sb = row * GSTR + hh * 32 + qp * 2;   // kk = (hh*8+c)*4 + 2*qp
#pragma unroll
                for (int c = 0; c < 8; c++) {
                    uint32_t h, l;
                    pk_hl(av[c], cv[c], h, l);            // (kw0, kw1) pair
                    *(uint32_t*)&sAh[sb + c * 4] = h;
                    *(uint32_t*)&sAl[sb + c * 4] = l;
                }
            }
        }
#pragma unroll
        for (int r = 0; r < 2; r++) {
            int f = tid + 256 * r;
            int row = f >> 3, kq = (f & 7) << 3;
            size_t gb = (size_t)(j0 + row) * K + k0 + kq;
            *(uint4*)&sBh[row * GSTR + kq] = *(const uint4*)&Bh[gb];
            *(uint4*)&sBl[row * GSTR + kq] = *(const uint4*)&Bl[gb];
        }
        __syncthreads();
        mma_chunk_lm(aAh, aAl, aBh, aBl, acc);
        __syncthreads();
    }

    if (issr) {
        float* out = xsf + (size_t)z * (B_ * M_ * C_);
#pragma unroll
        for (int mt = 0; mt < 2; mt++)
#pragma unroll
            for (int nt = 0; nt < 4; nt++) {
                int col = j0 + wn * 32 + nt * 8 + fc * 2;
                float bxv = bsr[col], byv = bsr[col + 1];
                int row0 = i0 + wm * 32 + mt * 16 + fr;
                *(float2*)&out[(size_t)row0 * C_ + col] =
                    make_float2(acc[mt][nt][0] + bxv, acc[mt][nt][1] + byv);
                *(float2*)&out[(size_t)(row0 + 8) * C_ + col] =
                    make_float2(acc[mt][nt][2] + bxv, acc[mt][nt][3] + byv);
            }
    } else {
        const float sc = 0.17677669529663687f * 1.4426950408889634f;
        __nv_bfloat16* oh = qhO + (size_t)z * NX;
        __nv_bfloat16* ol = qlO + (size_t)z * NX;
#pragma unroll
        for (int mt = 0; mt < 2; mt++)
#pragma unroll
            for (int nt = 0; nt < 4; nt++) {
                int col = j0 + wn * 32 + nt * 8 + fc * 2;
                int row0 = i0 + wm * 32 + mt * 16 + fr;
                st_split(oh, ol, (size_t)row0 * C_ + col,
                         acc[mt][nt][0] * sc, acc[mt][nt][1] * sc);
                st_split(oh, ol, (size_t)(row0 + 8) * C_ + col,
                         acc[mt][nt][2] * sc, acc[mt][nt][3] * sc);
            }
    }
}

// ---- generic GEMM (kv + proj), BK=64, ldmatrix fragments ----
__global__ __launch_bounds__(256)
void gemm_s(float* __restrict__ outf,
            __nv_bfloat16* __restrict__ outh, __nv_bfloat16* __restrict__ outl,
            const __nv_bfloat16* __restrict__ Ah, const __nv_bfloat16* __restrict__ Al,
            const __nv_bfloat16* __restrict__ Bh, const __nv_bfloat16* __restrict__ Bl,
            const float* __restrict__ bias, int Nc, int K,
            size_t strA, size_t strO, int splitout) {
    extern __shared__ __nv_bfloat16 sm[];
    __nv_bfloat16* sAh = sm;
    __nv_bfloat16* sAl = sm + 128 * GSTR;
    __nv_bfloat16* sBh = sm + 2 * 128 * GSTR;
    __nv_bfloat16* sBl = sm + 2 * 128 * GSTR + 64 * GSTR;

    const int z = blockIdx.z;
    Ah += z * strA; Al += z * strA;
    const int tid = threadIdx.x, wid = tid >> 5, lane = tid & 31;
    const int wm = wid & 3, wn = wid >> 2;
    const int fr = lane >> 2, fc = lane & 3;
    const int i0 = blockIdx.y * 128, j0 = blockIdx.x * 64;

    uint32_t aAh, aAl, aBh, aBl;
    lm_addrs(s2u(sm), lane, wm, wn, aAh, aAl, aBh, aBl);

    float acc[2][4][4] = {};

    for (int k0 = 0; k0 < K; k0 += 64) {
#pragma unroll
        for (int r = 0; r < 4; r++) {
            int f = tid + 256 * r;
            int row = f >> 3, kq = (f & 7) << 3;
            size_t ga = (size_t)(i0 + row) * K + k0 + kq;
            *(uint4*)&sAh[row * GSTR + kq] = *(const uint4*)&Ah[ga];
            *(uint4*)&sAl[row * GSTR + kq] = *(const uint4*)&Al[ga];
        }
#pragma unroll
        for (int r = 0; r < 2; r++) {
            int f = tid + 256 * r;
            int row = f >> 3, kq = (f & 7) << 3;
            size_t gb = (size_t)(j0 + row) * K + k0 + kq;
            *(uint4*)&sBh[row * GSTR + kq] = *(const uint4*)&Bh[gb];
            *(uint4*)&sBl[row * GSTR + kq] = *(const uint4*)&Bl[gb];
        }
        __syncthreads();
        mma_chunk_lm(aAh, aAl, aBh, aBl, acc);
        __syncthreads();
    }

    if (!splitout) {
        float* out = outf + z * strO;
#pragma unroll
        for (int mt = 0; mt < 2; mt++)
#pragma unroll
            for (int nt = 0; nt < 4; nt++) {
                int col = j0 + wn * 32 + nt * 8 + fc * 2;
                float bxv = 0.f, byv = 0.f;
                if (bias) { bxv = bias[col]; byv = bias[col + 1]; }
                int row0 = i0 + wm * 32 + mt * 16 + fr;
                *(float2*)&out[(size_t)row0 * Nc + col] =
                    make_float2(acc[mt][nt][0] + bxv, acc[mt][nt][1] + byv);
                *(float2*)&out[(size_t)(row0 + 8) * Nc + col] =
                    make_float2(acc[mt][nt][2] + bxv, acc[mt][nt][3] + byv);
            }
    } else {
        __nv_bfloat16* oh = outh + z * strO;
        __nv_bfloat16* ol = outl + z * strO;
#pragma unroll
        for (int mt = 0; mt < 2; mt++)
#pragma unroll
            for (int nt = 0; nt < 4; nt++) {
                int col = j0 + wn * 32 + nt * 8 + fc * 2;
                int row0 = i0 + wm * 32 + mt * 16 + fr;
                st_split(oh, ol, (size_t)row0 * Nc + col,
                         acc[mt][nt][0], acc[mt][nt][1]);
                st_split(oh, ol, (size_t)(row0 + 8) * Nc + col,
                         acc[mt][nt][2], acc[mt][nt][3]);
            }
    }
}

// ---------------- LayerNorm: warp per row, float4 IO ----------------
__global__ __launch_bounds__(256)
void layernorm_k(const float* __restrict__ xsf,
                 __nv_bfloat16* __restrict__ xsh, __nv_bfloat16* __restrict__ xsl,
                 const float* __restrict__ w0, const float* __restrict__ b0,
                 const float* __restrict__ w1, const float* __restrict__ b1) {
    int z = blockIdx.y;
    size_t zoff = (size_t)z * B_ * M_ * C_;
    const float* w = z ? w1 : w0;
    const float* bv = z ? b1 : b0;
    int row = blockIdx.x * 8 + (threadIdx.x >> 5);
    int lane = threadIdx.x & 31;
    const float* src = xsf + zoff + (size_t)row * C_ + lane * 8;
    float4 a = *(const float4*)src;
    float4 c = *(const float4*)(src + 4);
    float v[8] = {a.x, a.y, a.z, a.w, c.x, c.y, c.z, c.w};
    float s = 0.f, s2 = 0.f;
#pragma unroll
    for (int i = 0; i < 8; i++) { s += v[i]; s2 += v[i] * v[i]; }
#pragma unroll
    for (int o = 16; o > 0; o >>= 1) {
        s  += __shfl_xor_sync(~0u, s,  o);
        s2 += __shfl_xor_sync(~0u, s2, o);
    }
    float mu  = s * (1.f / C_);
    float var = s2 * (1.f / C_) - mu * mu;
    float inv = rsqrtf(var + 1e-5f);
    float4 wa = *(const float4*)&w[lane * 8];
    float4 wc = *(const float4*)&w[lane * 8 + 4];
    float4 ba = *(const float4*)&bv[lane * 8];
    float4 bc = *(const float4*)&bv[lane * 8 + 4];
    float wv[8] = {wa.x, wa.y, wa.z, wa.w, wc.x, wc.y, wc.z, wc.w};
    float bb[8] = {ba.x, ba.y, ba.z, ba.w, bc.x, bc.y, bc.z, bc.w};
    size_t o = zoff + (size_t)row * C_ + lane * 8;
#pragma unroll
    for (int i = 0; i < 4; i++) {
        float y0 = (v[2 * i]     - mu) * inv * wv[2 * i]     + bb[2 * i];
        float y1 = (v[2 * i + 1] - mu) * inv * wv[2 * i + 1] + bb[2 * i + 1];
        st_split(xsh, xsl, o + 2 * i, y0, y1);
    }
}

// ================ HMMA fused flash attention (reg-prefetch pipeline) ================
#define ASTR 40
#define VSTR 72
__global__ __launch_bounds__(256, 2)
void attention_k(__nv_bfloat16* __restrict__ aohB, __nv_bfloat16* __restrict__ aolB,
                 const __nv_bfloat16* __restrict__ qhB, const __nv_bfloat16* __restrict__ qlB,
                 const __nv_bfloat16* __restrict__ kvhB, const __nv_bfloat16* __restrict__ kvlB) {
    __shared__ __nv_bfloat16 qh[128][ASTR], ql[128][ASTR];
    __shared__ __nv_bfloat16 kh[64][ASTR],  kl[64][ASTR];
    __shared__ __nv_bfloat16 vhT[32][VSTR], vlT[32][VSTR];

    const int z = blockIdx.z;
    const size_t sQ  = (size_t)B_ * N_ * C_;
    const size_t sKV = (size_t)B_ * M_ * 2 * C_;
    const __nv_bfloat16* qgh = qhB + z * sQ;
    const __nv_bfloat16* qgl = qlB + z * sQ;
    const __nv_bfloat16* kvh = kvhB + z * sKV;
    const __nv_bfloat16* kvl = kvlB + z * sKV;
    __nv_bfloat16* aoh = aohB + z * sQ;
    __nv_bfloat16* aol = aolB + z * sQ;
    const int tid = threadIdx.x, wid = tid >> 5, lane = tid & 31;
    const int fr = lane >> 2, fc = lane & 3;
    const int bh = blockIdx.y;
    const int b = bh >> 3, h = bh & 7;
    const int r0 = blockIdx.x * 128;

    const size_t qbase = ((size_t)b * N_ + r0) * C_ + h * D_;
#pragma unroll
    for (int r = 0; r < 2; r++) {
        int idx = tid + 256 * r;
        int row = idx >> 2, kq = (idx & 3) << 3;
        *(uint4*)&qh[row][kq] = *(const uint4*)&qgh[qbase + (size_t)row * C_ + kq];
        *(uint4*)&ql[row][kq] = *(const uint4*)&qgl[qbase + (size_t)row * C_ + kq];
    }

    float m0 = -1e30f, m1 = -1e30f, l0 = 0.f, l1 = 0.f;
    float O[4][4] = {};
    const size_t kbase = (size_t)b * M_ * (2 * C_) + h * D_;

    const int kj = tid >> 2, kq4 = (tid & 3) << 3;
    const int vjp = tid >> 3, vdq = (tid & 7) << 2;
    uint4 pkh, pkl;
    uint2 pah, pch, pal, pcl;
    {
        size_t ga = kbase + (size_t)kj * (2 * C_) + kq4;
        pkh = *(const uint4*)&kvh[ga];
        pkl = *(const uint4*)&kvl[ga];
        size_t gv = kbase + (size_t)(2 * vjp) * (2 * C_) + C_ + vdq;
        pah = *(const uint2*)&kvh[gv];
        pch = *(const uint2*)&kvh[gv + 2 * C_];
        pal = *(const uint2*)&kvl[gv];
        pcl = *(const uint2*)&kvl[gv + 2 * C_];
    }

    for (int j0 = 0; j0 < M_; j0 += 64) {
        __syncthreads();
        *(uint4*)&kh[kj][kq4] = pkh;
        *(uint4*)&kl[kj][kq4] = pkl;
        *(uint32_t*)&vhT[vdq + 0][2 * vjp] = __byte_perm(pah.x, pch.x, 0x5410);
        *(uint32_t*)&vhT[vdq + 1][2 * vjp] = __byte_perm(pah.x, pch.x, 0x7632);
        *(uint32_t*)&vhT[vdq + 2][2 * vjp] = __byte_perm(pah.y, pch.y, 0x5410);
        *(uint32_t*)&vhT[vdq + 3][2 * vjp] = __byte_perm(pah.y, pch.y, 0x7632);
        *(uint32_t*)&vlT[vdq + 0][2 * vjp] = __byte_perm(pal.x, pcl.x, 0x5410);
        *(uint32_t*)&vlT[vdq + 1][2 * vjp] = __byte_perm(pal.x, pcl.x, 0x7632);
        *(uint32_t*)&vlT[vdq + 2][2 * vjp] = __byte_perm(pal.y, pcl.y, 0x5410);
        *(uint32_t*)&vlT[vdq + 3][2 * vjp] = __byte_perm(pal.y, pcl.y, 0x7632);
        __syncthreads();
        if (j0 + 64 < M_) {
            size_t ga = kbase + (size_t)(j0 + 64 + kj) * (2 * C_) + kq4;
            pkh = *(const uint4*)&kvh[ga];
            pkl = *(const uint4*)&kvl[ga];
            size_t gv = kbase + (size_t)(j0 + 64 + 2 * vjp) * (2 * C_) + C_ + vdq;
            pah = *(const uint2*)&kvh[gv];
            pch = *(const uint2*)&kvh[gv + 2 * C_];
            pal = *(const uint2*)&kvl[gv];
            pcl = *(const uint2*)&kvl[gv + 2 * C_];
        }

        float S[8][4] = {};
        const int arow = (wid << 4) + fr;
#pragma unroll
        for (int s = 0; s < 2; s++) {
            const int kb = (s << 4) + (fc << 1);
            uint32_t Ah[4], Al[4];
            Ah[0] = *(const uint32_t*)&qh[arow][kb];
            Ah[1] = *(const uint32_t*)&qh[arow + 8][kb];
            Ah[2] = *(const uint32_t*)&qh[arow][kb + 8];
            Ah[3] = *(const uint32_t*)&qh[arow + 8][kb + 8];
            Al[0] = *(const uint32_t*)&ql[arow][kb];
            Al[1] = *(const uint32_t*)&ql[arow + 8][kb];
            Al[2] = *(const uint32_t*)&ql[arow][kb + 8];
            Al[3] = *(const uint32_t*)&ql[arow + 8][kb + 8];
#pragma unroll
            for (int t = 0; t < 8; t++) {
                const int brow = (t << 3) + fr;
                uint32_t Bh[2], Bl[2];
                Bh[0] = *(const uint32_t*)&kh[brow][kb];
                Bh[1] = *(const uint32_t*)&kh[brow][kb + 8];
                Bl[0] = *(const uint32_t*)&kl[brow][kb];
                Bl[1] = *(const uint32_t*)&kl[brow][kb + 8];
                mma16816(S[t], Ah, Bh);
                mma16816(S[t], Ah, Bl);
                mma16816(S[t], Al, Bh);
            }
        }

        float cm0 = -1e30f, cm1 = -1e30f;
#pragma unroll
        for (int t = 0; t < 8; t++) {
            cm0 = fmaxf(cm0, fmaxf(S[t][0], S[t][1]));
            cm1 = fmaxf(cm1, fmaxf(S[t][2], S[t][3]));
        }
        cm0 = fmaxf(cm0, __shfl_xor_sync(~0u, cm0, 1));
        cm0 = fmaxf(cm0, __shfl_xor_sync(~0u, cm0, 2));
        cm1 = fmaxf(cm1, __shfl_xor_sync(~0u, cm1, 1));
        cm1 = fmaxf(cm1, __shfl_xor_sync(~0u, cm1, 2));
        float nm0 = fmaxf(m0, cm0), nm1 = fmaxf(m1, cm1);
        float corr0 = ex2(m0 - nm0), corr1 = ex2(m1 - nm1);
        m0 = nm0; m1 = nm1;
        float ps0 = 0.f, ps1 = 0.f;
#pragma unroll
        for (int t = 0; t < 8; t++) {
            S[t][0] = ex2(S[t][0] - nm0);
            S[t][1] = ex2(S[t][1] - nm0);
            S[t][2] = ex2(S[t][2] - nm1);
            S[t][3] = ex2(S[t][3] - nm1);
            ps0 += S[t][0] + S[t][1];
            ps1 += S[t][2] + S[t][3];
        }
        ps0 += __shfl_xor_sync(~0u, ps0, 1);
        ps0 += __shfl_xor_sync(~0u, ps0, 2);
        ps1 += __shfl_xor_sync(~0u, ps1, 1);
        ps1 += __shfl_xor_sync(~0u, ps1, 2);
        l0 = l0 * corr0 + ps0;
        l1 = l1 * corr1 + ps1;
#pragma unroll
        for (int u = 0; u < 4; u++) {
            O[u][0] *= corr0; O[u][1] *= corr0;
            O[u][2] *= corr1; O[u][3] *= corr1;
        }

#pragma unroll
        for (int s = 0; s < 4; s++) {
            uint32_t Ph[4], Pl[4];
            pk_hl(S[2 * s][0],     S[2 * s][1],     Ph[0], Pl[0]);
            pk_hl(S[2 * s][2],     S[2 * s][3],     Ph[1], Pl[1]);
            pk_hl(S[2 * s + 1][0], S[2 * s + 1][1], Ph[2], Pl[2]);
            pk_hl(S[2 * s + 1][2], S[2 * s + 1][3], Ph[3], Pl[3]);
            const int jb = (s << 4) + (fc << 1);
#pragma unroll
            for (int u = 0; u < 4; u++) {
                const int dn = (u << 3) + fr;
                uint32_t Bh[2], Bl[2];
                Bh[0] = *(const uint32_t*)&vhT[dn][jb];
                Bh[1] = *(const uint32_t*)&vhT[dn][jb + 8];
                Bl[0] = *(const uint32_t*)&vlT[dn][jb];
                Bl[1] = *(const uint32_t*)&vlT[dn][jb + 8];
                mma16816(O[u], Ph, Bh);
                mma16816(O[u], Ph, Bl);
                mma16816(O[u], Pl, Bh);
            }
        }
    }

    const float inv0 = 1.f / l0, inv1 = 1.f / l1;
    const size_t obase = ((size_t)b * N_ + r0) * C_ + h * D_;
    const int grow = (wid << 4) + fr;
#pragma unroll
    for (int u = 0; u < 4; u++) {
        int col = (u << 3) + (fc << 1);
        st_split(aoh, aol, obase + (size_t)grow * C_ + col,
                 O[u][0] * inv0, O[u][1] * inv0);
        st_split(aoh, aol, obase + (size_t)(grow + 8) * C_ + col,
                 O[u][2] * inv1, O[u][3] * inv1);
    }
}

// ---------------- launch ----------------
extern "C" void kernel_launch(void* const* d_in, const int* in_sizes, int n_in,
                              void* d_out, int out_size) {
    const float* x0     = (const float*)d_in[0];
    const float* x1     = (const float*)d_in[1];
    const float* Wq     = (const float*)d_in[2];
    const float* Wkv    = (const float*)d_in[3];
    const float* Wproj  = (const float*)d_in[4];
    const float* bproj  = (const float*)d_in[5];
    const float* Wsr    = (const float*)d_in[6];
    const float* bsr    = (const float*)d_in[7];
    const float* lnw0   = (const float*)d_in[8];
    const float* lnb0   = (const float*)d_in[9];
    const float* lnw1   = (const float*)d_in[10];
    const float* lnb1   = (const float*)d_in[11];
    float* out = (float*)d_out;

    __nv_bfloat16 *qh, *ql, *xsh, *xsl, *kvh, *kvl, *aoh, *aol;
    __nv_bfloat16 *wqh, *wql, *wkvh, *wkvl, *wprh, *wprl, *wsrh, *wsrl;
    float* xsf;
    cudaGetSymbolAddress((void**)&qh,   g_qh);   cudaGetSymbolAddress((void**)&ql,   g_ql);
    cudaGetSymbolAddress((void**)&xsf,  g_xsf);
    cudaGetSymbolAddress((void**)&xsh,  g_xsh);  cudaGetSymbolAddress((void**)&xsl,  g_xsl);
    cudaGetSymbolAddress((void**)&kvh,  g_kvh);  cudaGetSymbolAddress((void**)&kvl,  g_kvl);
    cudaGetSymbolAddress((void**)&aoh,  g_aoh);  cudaGetSymbolAddress((void**)&aol,  g_aol);
    cudaGetSymbolAddress((void**)&wqh,  g_wqh);  cudaGetSymbolAddress((void**)&wql,  g_wql);
    cudaGetSymbolAddress((void**)&wkvh, g_wkvh); cudaGetSymbolAddress((void**)&wkvl, g_wkvl);
    cudaGetSymbolAddress((void**)&wprh, g_wprh); cudaGetSymbolAddress((void**)&wprl, g_wprl);
    cudaGetSymbolAddress((void**)&wsrh, g_wsrh); cudaGetSymbolAddress((void**)&wsrl, g_wsrl);

    cudaFuncSetAttribute(gemm_s,
                         cudaFuncAttributeMaxDynamicSharedMemorySize, GSMEM_BYTES);
    cudaFuncSetAttribute(gemm_qsr,
                         cudaFuncAttributeMaxDynamicSharedMemorySize, GSMEM_BYTES);

    const size_t sQ  = (size_t)NX;
    const size_t sXS = (size_t)B_ * M_ * C_;
    const size_t sKV = (size_t)B_ * M_ * 2 * C_;

    // (1) split weights (x converted inline in gemm_qsr)
    split_w<<<512, 256>>>(wqh, wql, wkvh, wkvl, wprh, wprl, wsrh, wsrl,
                          Wq, Wkv, Wproj, Wsr);
    // (2) fused q-proj + SR-conv (im2col + fp32->split inline, ldmatrix)
    gemm_qsr<<<640, 256, GSMEM_BYTES>>>(x0, x1, wqh, wql, wsrh, wsrl,
                                        qh, ql, xsf, bsr);
    // (3) layernorm -> split (warp per row)
    layernorm_k<<<dim3((B_ * M_) / 8, 2), 256>>>(xsf, xsh, xsl,
                                                 lnw0, lnb0, lnw1, lnb1);
    // (4) kv = xs @ Wkv^T -> split (ldmatrix)
    gemm_s<<<dim3((2 * C_) / 64, (B_ * M_) / 128, 2), 256, GSMEM_BYTES>>>(
        nullptr, kvh, kvl, xsh, xsl, wkvh, wkvl, nullptr, 2 * C_, C_, sXS, sKV, 1);
    // (5) fused attention (pipelined)
    attention_k<<<dim3(N_ / 128, B_ * H_, 2), 256>>>(aoh, aol, qh, ql, kvh, kvl);
    // (6) y = ao @ Wproj^T + bproj (ldmatrix)
    gemm_s<<<dim3(C_ / 64, (B_ * N_) / 128, 2), 256, GSMEM_BYTES>>>(
        out, nullptr, nullptr, aoh, aol, wprh, wprl, bproj, C_, C_, sQ, sQ, 0);
}